// round 13
// baseline (speedup 1.0000x reference)
#include <cuda_runtime.h>
#include <cuda_fp16.h>
#include <math.h>
#include <stdint.h>

#define BB 128
#define TT 100
#define PD 4096
#define HG 512
#define HD 128
#define GH 261
#define GG 783
#define ZD 64
#define XD 256

__device__ __half g_projh[BB*TT*PD];   // fp16 activations (b*T+t, 4096)
__device__ __half g_Wih16[HG*PD];      // fp16 lstm_Wih
__device__ float g_xg[TT*BB*HG];       // (t,b,512)
__device__ uint2 g_gT[25*GG];          // gru Whh k=160..259 fp16 packs: [p][g]
__device__ float4 g_W1T4[66*ZD];       // jf_W1 packs (zero-padded past 261)
__device__ float g_gxbase[BB*GG];

__device__ __forceinline__ float sigmoidf_(float x){ return 1.0f/(1.0f+expf(-x)); }
__device__ __forceinline__ float leakyf_(float x, float s){ return x >= 0.0f ? x : s*x; }
__device__ __forceinline__ void fma2(unsigned long long& a, unsigned long long w, unsigned long long h){
    asm("fma.rn.f32x2 %0, %1, %2, %0;" : "+l"(a) : "l"(w), "l"(h));
}
__device__ __forceinline__ unsigned long long pack2(float lo, float hi){
    unsigned long long r;
    asm("mov.b64 %0, {%1,%2};" : "=l"(r) : "f"(lo), "f"(hi));
    return r;
}
__device__ __forceinline__ void cp16(void* s, const void* g){
    unsigned ss = (unsigned)__cvta_generic_to_shared(s);
    asm volatile("cp.async.cg.shared.global [%0], [%1], 16;\n" :: "r"(ss), "l"(g));
}
#define MMA_F16(c, au, bu) \
  asm volatile("mma.sync.aligned.m16n8k16.row.col.f32.f16.f16.f32 " \
    "{%0,%1,%2,%3},{%4,%5,%6,%7},{%8,%9},{%0,%1,%2,%3};\n" \
    : "+f"(c[0]),"+f"(c[1]),"+f"(c[2]),"+f"(c[3]) \
    : "r"(au[0]),"r"(au[1]),"r"(au[2]),"r"(au[3]),"r"(bu[0]),"r"(bu[1]))

// K1: proj (blocks 0..1599) + weight prep (blocks 1600..1759), fused.
__global__ void __launch_bounds__(512) k_proj(const float* __restrict__ pose,
                                              const float* __restrict__ W,
                                              const float* __restrict__ bias,
                                              const float* __restrict__ Wih,
                                              const float* __restrict__ gWhh,
                                              const float* __restrict__ W1)
{
    int tid = threadIdx.x;
    if (blockIdx.x >= 1600){
        int i0 = (blockIdx.x - 1600)*512 + tid;
        int st = 160*512;
        for (int i = i0; i < HG*PD; i += st)
            g_Wih16[i] = __float2half_rn(Wih[i]);
        for (int i = i0; i < 25*GG; i += st){
            int p = i / GG, g = i - p*GG;
            const float* r = gWhh + (size_t)g*GH + 160 + 4*p;
            __half2 lo = __floats2half2_rn(r[0], r[1]);
            __half2 hi = __floats2half2_rn(r[2], r[3]);
            uint2 v;
            v.x = *(unsigned*)&lo;
            v.y = *(unsigned*)&hi;
            g_gT[i] = v;
        }
        for (int i = i0; i < 66*ZD; i += st){
            int p = i >> 6, o = i & 63;
            const float* r = W1 + (size_t)o*GH;
            int k = 4*p;
            float4 v;
            v.x = (k   < GH) ? r[k]   : 0.f;
            v.y = (k+1 < GH) ? r[k+1] : 0.f;
            v.z = (k+2 < GH) ? r[k+2] : 0.f;
            v.w = (k+3 < GH) ? r[k+3] : 0.f;
            g_W1T4[i] = v;
        }
        return;
    }
    __shared__ float p[8][9];
    int r0 = blockIdx.x*8;
    if (tid < 72) p[tid/9][tid%9] = pose[r0*9 + tid];
    __syncthreads();
#pragma unroll
    for (int i = 0; i < 8; i++){
        int k = tid + i*512;
        const float* w = W + k*9;
        float wv[9];
#pragma unroll
        for (int j = 0; j < 9; j++) wv[j] = w[j];
        float bk = bias[k];
#pragma unroll
        for (int r = 0; r < 8; r++){
            float acc = bk;
#pragma unroll
            for (int j = 0; j < 9; j++) acc += wv[j]*p[r][j];
            g_projh[(size_t)(r0+r)*PD + k] = __float2half_rn(leakyf_(acc, 0.1f));
        }
    }
}

// K2: fp16 mma.sync GEMM (at scalar-pipe roofline; unchanged)
#define SMSH 72
#define KC 64
__global__ void __launch_bounds__(256, 2) k_gemm(const float* __restrict__ bih,
                                                 const float* __restrict__ bhh)
{
    extern __shared__ __align__(16) char smc[];
    __half* Ash = (__half*)smc;                       // [2][128][72]
    __half* Bsh = (__half*)(smc + 2*128*SMSH*2);      // [2][128][72]
    int tid = threadIdx.x, lane = tid & 31, warp = tid >> 5;
    int bn = blockIdx.x, bm = blockIdx.y;
    const __half* Ag = g_projh + (size_t)bm*128*PD;
    const __half* Bg = g_Wih16 + (size_t)bn*128*PD;
    int wm = warp >> 2, wn = warp & 3;
    float acc[4][4][4];
#pragma unroll
    for (int a = 0; a < 4; a++)
#pragma unroll
        for (int b = 0; b < 4; b++)
#pragma unroll
            for (int c = 0; c < 4; c++) acc[a][b][c] = 0.f;

    for (int i = tid; i < 1024; i += 256){
        int row = i >> 3, sub = i & 7;
        cp16(Ash + row*SMSH + sub*8, Ag + (size_t)row*PD + sub*8);
    }
    for (int i = tid; i < 1024; i += 256){
        int row = i >> 3, sub = i & 7;
        cp16(Bsh + row*SMSH + sub*8, Bg + (size_t)row*PD + sub*8);
    }
    asm volatile("cp.async.commit_group;\n");

    for (int c = 0; c < PD/KC; c++){
        int buf = c & 1;
        if (c+1 < PD/KC){
            int nb = buf^1;
            int kof = (c+1)*KC;
            for (int i = tid; i < 1024; i += 256){
                int row = i >> 3, sub = i & 7;
                cp16(Ash + nb*128*SMSH + row*SMSH + sub*8, Ag + (size_t)row*PD + kof + sub*8);
            }
            for (int i = tid; i < 1024; i += 256){
                int row = i >> 3, sub = i & 7;
                cp16(Bsh + nb*128*SMSH + row*SMSH + sub*8, Bg + (size_t)row*PD + kof + sub*8);
            }
        }
        asm volatile("cp.async.commit_group;\n");
        asm volatile("cp.async.wait_group 1;\n");
        __syncthreads();
        const uint32_t* A = (const uint32_t*)(Ash + buf*128*SMSH);
        const uint32_t* B = (const uint32_t*)(Bsh + buf*128*SMSH);
#pragma unroll
        for (int kk = 0; kk < 4; kk++){
            int kw = kk*8 + (lane & 3);
            uint32_t au[4][4], bu[4][2];
#pragma unroll
            for (int mt = 0; mt < 4; mt++){
                int r = wm*64 + mt*16 + (lane>>2);
                au[mt][0] = A[r*36 + kw];
                au[mt][1] = A[(r+8)*36 + kw];
                au[mt][2] = A[r*36 + kw + 4];
                au[mt][3] = A[(r+8)*36 + kw + 4];
            }
#pragma unroll
            for (int nt = 0; nt < 4; nt++){
                int n = wn*32 + nt*8 + (lane>>2);
                bu[nt][0] = B[n*36 + kw];
                bu[nt][1] = B[n*36 + kw + 4];
            }
#pragma unroll
            for (int mt = 0; mt < 4; mt++)
#pragma unroll
                for (int nt = 0; nt < 4; nt++)
                    MMA_F16(acc[mt][nt], au[mt], bu[nt]);
        }
        __syncthreads();
    }
#pragma unroll
    for (int mt = 0; mt < 4; mt++){
#pragma unroll
        for (int nt = 0; nt < 4; nt++){
            int col = bn*128 + wn*32 + nt*8 + (lane&3)*2;
            float bs0 = bih[col]   + bhh[col];
            float bs1 = bih[col+1] + bhh[col+1];
            int r0 = bm*128 + wm*64 + mt*16 + (lane>>2);
            int b0i = r0/TT, t0 = r0 - b0i*TT;
            *(float2*)(g_xg + (size_t)t0*(BB*HG) + b0i*HG + col) =
                make_float2(acc[mt][nt][0]+bs0, acc[mt][nt][1]+bs1);
            int r1 = r0 + 8;
            int b1i = r1/TT, t1 = r1 - b1i*TT;
            *(float2*)(g_xg + (size_t)t1*(BB*HG) + b1i*HG + col) =
                make_float2(acc[mt][nt][2]+bs0, acc[mt][nt][3]+bs1);
        }
    }
}

// K3: LSTM scan nb=1 + fused head (unchanged from R12)
__global__ void __launch_bounds__(512) k_lstm(
    const float* __restrict__ Whh,
    const float* __restrict__ eps,
    const float* __restrict__ muW, const float* __restrict__ mub,
    const float* __restrict__ lvW, const float* __restrict__ lvb,
    const float* __restrict__ fcW, const float* __restrict__ fcb,
    const float* __restrict__ gWih, const float* __restrict__ gbih,
    float* __restrict__ out)
{
    extern __shared__ float sm[];
    ulonglong2* wsu2 = (ulonglong2*)sm;          // [16][512]: k=64..127
    float* hs = sm + 32768;                      // 128
    float* gs = hs + 128;                        // 512
    float* mu_s = gs + 512;                      // 64
    float* lv_s = mu_s + 64;                     // 64
    float* emb  = lv_s + 64;                     // 64
    float* xs   = emb + 64;                      // 256
    int tid = threadIdx.x, b = blockIdx.x;

    const ulonglong2* wrow = (const ulonglong2*)(Whh + (size_t)tid*HD);
    unsigned long long wr2[32];
#pragma unroll
    for (int i = 0; i < 16; i++){
        ulonglong2 v = wrow[i];
        wr2[2*i] = v.x; wr2[2*i+1] = v.y;
    }
#pragma unroll
    for (int i = 0; i < 16; i++) wsu2[i*512 + tid] = wrow[16+i];
    if (tid < HD) hs[tid] = 0.f;
    float c = 0.f;
    __syncthreads();
    const float* xg = g_xg + b*HG + tid;
    float xcur = xg[0];
    for (int t = 0; t < TT; t++){
        float xnext = (t < TT-1) ? xg[(size_t)(t+1)*(BB*HG)] : 0.f;
        const ulonglong2* H2 = (const ulonglong2*)hs;
        unsigned long long a2 = 0ull, c2 = 0ull, d2 = 0ull, e2 = 0ull;
#pragma unroll
        for (int i = 0; i < 8; i++){
            ulonglong2 h0 = H2[2*i], h1 = H2[2*i+1];
            fma2(a2, wr2[4*i],   h0.x);
            fma2(c2, wr2[4*i+1], h0.y);
            fma2(d2, wr2[4*i+2], h1.x);
            fma2(e2, wr2[4*i+3], h1.y);
        }
#pragma unroll
        for (int i = 0; i < 8; i++){
            ulonglong2 w0 = wsu2[(2*i)*512 + tid];
            ulonglong2 w1 = wsu2[(2*i+1)*512 + tid];
            ulonglong2 h0 = H2[16+2*i], h1 = H2[17+2*i];
            fma2(a2, w0.x, h0.x);
            fma2(c2, w0.y, h0.y);
            fma2(d2, w1.x, h1.x);
            fma2(e2, w1.y, h1.y);
        }
        float a0,a1,b0,b1,d0,d1,e0,e1;
        asm("mov.b64 {%0,%1}, %2;" : "=f"(a0), "=f"(a1) : "l"(a2));
        asm("mov.b64 {%0,%1}, %2;" : "=f"(b0), "=f"(b1) : "l"(c2));
        asm("mov.b64 {%0,%1}, %2;" : "=f"(d0), "=f"(d1) : "l"(d2));
        asm("mov.b64 {%0,%1}, %2;" : "=f"(e0), "=f"(e1) : "l"(e2));
        gs[tid] = xcur + ((a0+a1) + (b0+b1)) + ((d0+d1) + (e0+e1));
        __syncthreads();
        if (tid < HD){
            float ii = sigmoidf_(gs[tid]);
            float ff = sigmoidf_(gs[HD+tid]);
            float gg = tanhf(gs[2*HD+tid]);
            float oo = sigmoidf_(gs[3*HD+tid]);
            c = ff*c + ii*gg;
            hs[tid] = oo*tanhf(c);
        }
        __syncthreads();
        xcur = xnext;
    }
    if (tid < 2*ZD){
        int o = tid & 63;
        const float* W = (tid < ZD) ? (muW + o*HD) : (lvW + o*HD);
        float acc = (tid < ZD) ? mub[o] : lvb[o];
        for (int k = 0; k < HD; k++) acc += W[k]*hs[k];
        acc = leakyf_(acc, 0.1f);
        if (tid < ZD) mu_s[o] = acc;
        else          lv_s[o] = fminf(10.f, fmaxf(-10.f, acc));
    }
    __syncthreads();
    if (tid < ZD){
        float m = mu_s[tid], lv = lv_s[tid];
        out[BB*TT*9 + b*ZD + tid] = m;
        out[BB*TT*9 + BB*ZD + b*ZD + tid] = lv;
        emb[tid] = m + eps[b*ZD + tid]*expf(0.5f*lv);
    }
    __syncthreads();
    if (tid < XD){
        float acc = fcb[tid];
        const float* W = fcW + tid*ZD;
        for (int k = 0; k < ZD; k++) acc += W[k]*emb[k];
        xs[tid] = acc;
    }
    __syncthreads();
    for (int g = tid; g < GG; g += 512){
        float acc = gbih[g];
        const float* W = gWih + (size_t)g*GH;
        for (int k = 0; k < XD; k++) acc += W[k]*xs[k];
        g_gxbase[(size_t)b*GG + g] = acc;
    }
}

// K5: GRU scan nb=1, 128 blocks, 864 threads.
// Weights: k=0..31 fp32 regs, k=32..159 fp16 smem, k=160..259 fp16 global.
__global__ void __launch_bounds__(864) k_gru(
    const float* __restrict__ noise_eps,
    const float* __restrict__ gWih, const float* __restrict__ gWhh,
    const float* __restrict__ gbhh,
    const float* __restrict__ b1,
    const float* __restrict__ W2, const float* __restrict__ b2,
    float* __restrict__ out)
{
    extern __shared__ float sm[];
    uint2* wsmH = (uint2*)sm;            // [32][784] fp16 packs k=32..159
    float* hb   = sm + 50176;            // 264 (zero-padded)
    float* sums = hb + 264;              // 784
    float* ghn  = sums + 784;            // 264
    float* f1s  = ghn + 264;             // 64
    float* nsAll= f1s + 64;              // [TT][4]
    int tid = threadIdx.x;
    int b = blockIdx.x;

    for (int j = tid; j < 264; j += 864) hb[j] = 0.f;
    for (int j = tid; j < TT*4; j += 864)
        nsAll[j] = noise_eps[(j>>2)*(BB*4) + b*4 + (j&3)] * 0.1f;

    unsigned long long wr2[16];
    float w260=0,wn0=0,wn1=0,wn2=0,wn3=0,wt=0,bh=0,gxb=0;
    if (tid < GG){
        const float* row = gWhh + (size_t)tid*GH;
#pragma unroll
        for (int i = 0; i < 16; i++) wr2[i] = pack2(row[2*i], row[2*i+1]);
#pragma unroll
        for (int p = 0; p < 32; p++){
            __half2 lo = __floats2half2_rn(row[32+4*p], row[33+4*p]);
            __half2 hi = __floats2half2_rn(row[34+4*p], row[35+4*p]);
            uint2 v;
            v.x = *(unsigned*)&lo;
            v.y = *(unsigned*)&hi;
            wsmH[p*784 + tid] = v;
        }
        w260 = row[260];
        const float* Wi = gWih + (size_t)tid*GH;
        wn0=Wi[256]; wn1=Wi[257]; wn2=Wi[258]; wn3=Wi[259]; wt=Wi[260];
        bh = gbhh[tid];
        gxb = g_gxbase[(size_t)b*GG + tid];
    }
    __syncthreads();
    const float inv = 1.0f/(float)(TT-1);
    for (int t = 0; t <= TT; t++){
        if (t < TT && tid < GG){
            const float* nsp = nsAll + t*4;
            float tv = (float)t * inv;
            float gx = gxb + wn0*nsp[0]+wn1*nsp[1]+wn2*nsp[2]+wn3*nsp[3] + wt*tv;
            unsigned long long acc = 0ull;
            const unsigned long long* H = (const unsigned long long*)hb;
#pragma unroll
            for (int i = 0; i < 16; i++) fma2(acc, wr2[i], H[i]);
#pragma unroll
            for (int p = 0; p < 32; p++){
                uint2 w = wsmH[p*784 + tid];
                float2 lo = __half22float2(*(const __half2*)&w.x);
                float2 hi = __half22float2(*(const __half2*)&w.y);
                fma2(acc, pack2(lo.x, lo.y), H[16+2*p]);
                fma2(acc, pack2(hi.x, hi.y), H[17+2*p]);
            }
            const uint2* gw = g_gT + tid;
#pragma unroll 5
            for (int p = 0; p < 25; p++){
                uint2 w = gw[(size_t)p*GG];
                float2 lo = __half22float2(*(const __half2*)&w.x);
                float2 hi = __half22float2(*(const __half2*)&w.y);
                fma2(acc, pack2(lo.x, lo.y), H[80+2*p]);
                fma2(acc, pack2(hi.x, hi.y), H[81+2*p]);
            }
            float s0, s1;
            asm("mov.b64 {%0,%1}, %2;" : "=f"(s0), "=f"(s1) : "l"(acc));
            float gh = bh + (s0+s1) + w260*hb[260];
            float v = gx + gh;
            if (tid >= 522){ v = gx; ghn[tid-522] = gh; }
            sums[tid] = v;
        }
        if (t >= 1 && tid >= 784 && tid < 848){
            int o = tid - 784;
            const float4* hv = (const float4*)hb;
            const float4* Wv = g_W1T4 + o;
            float acc = b1[o];
#pragma unroll
            for (int p = 0; p < 66; p++){
                float4 w = Wv[p*ZD];
                float4 h = hv[p];
                acc += w.x*h.x + w.y*h.y + w.z*h.z + w.w*h.w;
            }
            f1s[o] = leakyf_(acc, 0.2f);
        }
        __syncthreads();
        if (t < TT && tid < GH){
            float r = sigmoidf_(sums[tid]);
            float z = sigmoidf_(sums[GH+tid]);
            float n = tanhf(sums[2*GH+tid] + r*ghn[tid]);
            hb[tid] = (1.f - z)*n + z*hb[tid];
        }
        if (t >= 1 && tid >= 784 && tid < 793){
            int i = tid - 784;
            float acc = b2[i];
            const float* W = W2 + i*ZD;
            for (int o = 0; o < ZD; o++) acc += W[o]*f1s[o];
            out[(size_t)b*(TT*9) + (t-1)*9 + i] = sigmoidf_(acc);
        }
        __syncthreads();
    }
}

extern "C" void kernel_launch(void* const* d_in, const int* in_sizes, int n_in,
                              void* d_out, int out_size)
{
    const float* input_data = (const float*)d_in[0];
    const float* eps        = (const float*)d_in[1];
    const float* noise_eps  = (const float*)d_in[2];
    const float* proj_W     = (const float*)d_in[3];
    const float* proj_b     = (const float*)d_in[4];
    const float* lstm_Wih   = (const float*)d_in[5];
    const float* lstm_Whh   = (const float*)d_in[6];
    const float* lstm_bih   = (const float*)d_in[7];
    const float* lstm_bhh   = (const float*)d_in[8];
    const float* mu_W       = (const float*)d_in[9];
    const float* mu_b       = (const float*)d_in[10];
    const float* lv_W       = (const float*)d_in[11];
    const float* lv_b       = (const float*)d_in[12];
    const float* fcin_W     = (const float*)d_in[13];
    const float* fcin_b     = (const float*)d_in[14];
    const float* gru_Wih    = (const float*)d_in[15];
    const float* gru_Whh    = (const float*)d_in[16];
    const float* gru_bih    = (const float*)d_in[17];
    const float* gru_bhh    = (const float*)d_in[18];
    const float* jf_W1      = (const float*)d_in[19];
    const float* jf_b1      = (const float*)d_in[20];
    const float* jf_W2      = (const float*)d_in[21];
    const float* jf_b2      = (const float*)d_in[22];
    float* out = (float*)d_out;

    int gemm_smem = 2*2*128*SMSH*2;
    int lstm_smem = 32768*4 + (128 + 512 + 64 + 64 + 64 + 256)*4;
    int gru_smem  = (50176 + 264 + 784 + 264 + 64 + TT*4)*4;   // 207,808 B
    cudaFuncSetAttribute(k_gemm, cudaFuncAttributeMaxDynamicSharedMemorySize, gemm_smem);
    cudaFuncSetAttribute(k_lstm, cudaFuncAttributeMaxDynamicSharedMemorySize, lstm_smem);
    cudaFuncSetAttribute(k_gru,  cudaFuncAttributeMaxDynamicSharedMemorySize, gru_smem);

    k_proj<<<1760, 512>>>(input_data, proj_W, proj_b,
                          lstm_Wih, gru_Whh, jf_W1);
    dim3 g2(HG/128, TT*BB/128);   // (4, 100)
    k_gemm<<<g2, 256, gemm_smem>>>(lstm_bih, lstm_bhh);
    k_lstm<<<BB, 512, lstm_smem>>>(lstm_Whh, eps, mu_W, mu_b, lv_W, lv_b,
                                   fcin_W, fcin_b, gru_Wih, gru_bih, out);
    k_gru<<<BB, 864, gru_smem>>>(noise_eps, gru_Wih, gru_Whh, gru_bhh,
                                 jf_b1, jf_W2, jf_b2, out);
}

// round 14
// speedup vs baseline: 1.0670x; 1.0670x over previous
#include <cuda_runtime.h>
#include <cuda_fp16.h>
#include <math.h>
#include <stdint.h>

#define BB 128
#define TT 100
#define PD 4096
#define HG 512
#define HD 128
#define GH 261
#define GG 783
#define ZD 64
#define XD 256

__device__ __half g_projh[BB*TT*PD];   // fp16 activations (b*T+t, 4096)
__device__ __half g_Wih16[HG*PD];      // fp16 lstm_Wih
__device__ float g_xg[TT*BB*HG];       // (t,b,512)
__device__ float4 g_gWhh4[41*GG];      // gru Whh k=96..259: [p][g]
__device__ float4 g_W1T4[66*ZD];       // jf_W1 packs (zero-padded past 261)
__device__ float g_gxbase[BB*GG];

__device__ __forceinline__ float sigmoidf_(float x){ return 1.0f/(1.0f+expf(-x)); }
__device__ __forceinline__ float leakyf_(float x, float s){ return x >= 0.0f ? x : s*x; }
__device__ __forceinline__ void fma2(unsigned long long& a, unsigned long long w, unsigned long long h){
    asm("fma.rn.f32x2 %0, %1, %2, %0;" : "+l"(a) : "l"(w), "l"(h));
}
__device__ __forceinline__ void cp16(void* s, const void* g){
    unsigned ss = (unsigned)__cvta_generic_to_shared(s);
    asm volatile("cp.async.cg.shared.global [%0], [%1], 16;\n" :: "r"(ss), "l"(g));
}
#define MMA_F16(c, au, bu) \
  asm volatile("mma.sync.aligned.m16n8k16.row.col.f32.f16.f16.f32 " \
    "{%0,%1,%2,%3},{%4,%5,%6,%7},{%8,%9},{%0,%1,%2,%3};\n" \
    : "+f"(c[0]),"+f"(c[1]),"+f"(c[2]),"+f"(c[3]) \
    : "r"(au[0]),"r"(au[1]),"r"(au[2]),"r"(au[3]),"r"(bu[0]),"r"(bu[1]))

// K1: proj (blocks 0..1599) + weight prep (blocks 1600..1759), fused.
__global__ void __launch_bounds__(512) k_proj(const float* __restrict__ pose,
                                              const float* __restrict__ W,
                                              const float* __restrict__ bias,
                                              const float* __restrict__ Wih,
                                              const float* __restrict__ gWhh,
                                              const float* __restrict__ W1)
{
    int tid = threadIdx.x;
    if (blockIdx.x >= 1600){
        int i0 = (blockIdx.x - 1600)*512 + tid;
        int st = 160*512;
        for (int i = i0; i < HG*PD; i += st)
            g_Wih16[i] = __float2half_rn(Wih[i]);
        for (int i = i0; i < 41*GG; i += st){
            int p = i / GG, g = i - p*GG;
            const float* r = gWhh + (size_t)g*GH + 96 + 4*p;
            g_gWhh4[i] = make_float4(r[0], r[1], r[2], r[3]);
        }
        for (int i = i0; i < 66*ZD; i += st){
            int p = i >> 6, o = i & 63;
            const float* r = W1 + (size_t)o*GH;
            int k = 4*p;
            float4 v;
            v.x = (k   < GH) ? r[k]   : 0.f;
            v.y = (k+1 < GH) ? r[k+1] : 0.f;
            v.z = (k+2 < GH) ? r[k+2] : 0.f;
            v.w = (k+3 < GH) ? r[k+3] : 0.f;
            g_W1T4[i] = v;
        }
        return;
    }
    __shared__ float p[8][9];
    int r0 = blockIdx.x*8;
    if (tid < 72) p[tid/9][tid%9] = pose[r0*9 + tid];
    __syncthreads();
#pragma unroll
    for (int i = 0; i < 8; i++){
        int k = tid + i*512;
        const float* w = W + k*9;
        float wv[9];
#pragma unroll
        for (int j = 0; j < 9; j++) wv[j] = w[j];
        float bk = bias[k];
#pragma unroll
        for (int r = 0; r < 8; r++){
            float acc = bk;
#pragma unroll
            for (int j = 0; j < 9; j++) acc += wv[j]*p[r][j];
            g_projh[(size_t)(r0+r)*PD + k] = __float2half_rn(leakyf_(acc, 0.1f));
        }
    }
}

// K2: fp16 mma.sync GEMM (at scalar-pipe roofline; unchanged)
#define SMSH 72
#define KC 64
__global__ void __launch_bounds__(256, 2) k_gemm(const float* __restrict__ bih,
                                                 const float* __restrict__ bhh)
{
    extern __shared__ __align__(16) char smc[];
    __half* Ash = (__half*)smc;                       // [2][128][72]
    __half* Bsh = (__half*)(smc + 2*128*SMSH*2);      // [2][128][72]
    int tid = threadIdx.x, lane = tid & 31, warp = tid >> 5;
    int bn = blockIdx.x, bm = blockIdx.y;
    const __half* Ag = g_projh + (size_t)bm*128*PD;
    const __half* Bg = g_Wih16 + (size_t)bn*128*PD;
    int wm = warp >> 2, wn = warp & 3;
    float acc[4][4][4];
#pragma unroll
    for (int a = 0; a < 4; a++)
#pragma unroll
        for (int b = 0; b < 4; b++)
#pragma unroll
            for (int c = 0; c < 4; c++) acc[a][b][c] = 0.f;

    for (int i = tid; i < 1024; i += 256){
        int row = i >> 3, sub = i & 7;
        cp16(Ash + row*SMSH + sub*8, Ag + (size_t)row*PD + sub*8);
    }
    for (int i = tid; i < 1024; i += 256){
        int row = i >> 3, sub = i & 7;
        cp16(Bsh + row*SMSH + sub*8, Bg + (size_t)row*PD + sub*8);
    }
    asm volatile("cp.async.commit_group;\n");

    for (int c = 0; c < PD/KC; c++){
        int buf = c & 1;
        if (c+1 < PD/KC){
            int nb = buf^1;
            int kof = (c+1)*KC;
            for (int i = tid; i < 1024; i += 256){
                int row = i >> 3, sub = i & 7;
                cp16(Ash + nb*128*SMSH + row*SMSH + sub*8, Ag + (size_t)row*PD + kof + sub*8);
            }
            for (int i = tid; i < 1024; i += 256){
                int row = i >> 3, sub = i & 7;
                cp16(Bsh + nb*128*SMSH + row*SMSH + sub*8, Bg + (size_t)row*PD + kof + sub*8);
            }
        }
        asm volatile("cp.async.commit_group;\n");
        asm volatile("cp.async.wait_group 1;\n");
        __syncthreads();
        const uint32_t* A = (const uint32_t*)(Ash + buf*128*SMSH);
        const uint32_t* B = (const uint32_t*)(Bsh + buf*128*SMSH);
#pragma unroll
        for (int kk = 0; kk < 4; kk++){
            int kw = kk*8 + (lane & 3);
            uint32_t au[4][4], bu[4][2];
#pragma unroll
            for (int mt = 0; mt < 4; mt++){
                int r = wm*64 + mt*16 + (lane>>2);
                au[mt][0] = A[r*36 + kw];
                au[mt][1] = A[(r+8)*36 + kw];
                au[mt][2] = A[r*36 + kw + 4];
                au[mt][3] = A[(r+8)*36 + kw + 4];
            }
#pragma unroll
            for (int nt = 0; nt < 4; nt++){
                int n = wn*32 + nt*8 + (lane>>2);
                bu[nt][0] = B[n*36 + kw];
                bu[nt][1] = B[n*36 + kw + 4];
            }
#pragma unroll
            for (int mt = 0; mt < 4; mt++)
#pragma unroll
                for (int nt = 0; nt < 4; nt++)
                    MMA_F16(acc[mt][nt], au[mt], bu[nt]);
        }
        __syncthreads();
    }
#pragma unroll
    for (int mt = 0; mt < 4; mt++){
#pragma unroll
        for (int nt = 0; nt < 4; nt++){
            int col = bn*128 + wn*32 + nt*8 + (lane&3)*2;
            float bs0 = bih[col]   + bhh[col];
            float bs1 = bih[col+1] + bhh[col+1];
            int r0 = bm*128 + wm*64 + mt*16 + (lane>>2);
            int b0i = r0/TT, t0 = r0 - b0i*TT;
            *(float2*)(g_xg + (size_t)t0*(BB*HG) + b0i*HG + col) =
                make_float2(acc[mt][nt][0]+bs0, acc[mt][nt][1]+bs1);
            int r1 = r0 + 8;
            int b1i = r1/TT, t1 = r1 - b1i*TT;
            *(float2*)(g_xg + (size_t)t1*(BB*HG) + b1i*HG + col) =
                make_float2(acc[mt][nt][2]+bs0, acc[mt][nt][3]+bs1);
        }
    }
}

// K3: LSTM scan nb=1 + fused head; weight split 40 reg-pairs / 24 smem-pairs
__global__ void __launch_bounds__(512) k_lstm(
    const float* __restrict__ Whh,
    const float* __restrict__ eps,
    const float* __restrict__ muW, const float* __restrict__ mub,
    const float* __restrict__ lvW, const float* __restrict__ lvb,
    const float* __restrict__ fcW, const float* __restrict__ fcb,
    const float* __restrict__ gWih, const float* __restrict__ gbih,
    float* __restrict__ out)
{
    extern __shared__ float sm[];
    ulonglong2* wsu2 = (ulonglong2*)sm;          // [12][512]: k=80..127
    float* hs = sm + 24576;                      // 128
    float* gs = hs + 128;                        // 512
    float* mu_s = gs + 512;                      // 64
    float* lv_s = mu_s + 64;                     // 64
    float* emb  = lv_s + 64;                     // 64
    float* xs   = emb + 64;                      // 256
    int tid = threadIdx.x, b = blockIdx.x;

    const ulonglong2* wrow = (const ulonglong2*)(Whh + (size_t)tid*HD);
    unsigned long long wr2[40];                  // pairs 0..39 (k=0..79)
#pragma unroll
    for (int i = 0; i < 20; i++){
        ulonglong2 v = wrow[i];
        wr2[2*i] = v.x; wr2[2*i+1] = v.y;
    }
#pragma unroll
    for (int i = 0; i < 12; i++) wsu2[i*512 + tid] = wrow[20+i];
    if (tid < HD) hs[tid] = 0.f;
    float c = 0.f;
    __syncthreads();
    const float* xg = g_xg + b*HG + tid;
    float xcur = xg[0];
    for (int t = 0; t < TT; t++){
        float xnext = (t < TT-1) ? xg[(size_t)(t+1)*(BB*HG)] : 0.f;
        const ulonglong2* H2 = (const ulonglong2*)hs;   // 32 entries
        unsigned long long a2 = 0ull, c2 = 0ull, d2 = 0ull, e2 = 0ull;
#pragma unroll
        for (int i = 0; i < 10; i++){                   // pairs 0..39, H2[0..19]
            ulonglong2 h0 = H2[2*i], h1 = H2[2*i+1];
            fma2(a2, wr2[4*i],   h0.x);
            fma2(c2, wr2[4*i+1], h0.y);
            fma2(d2, wr2[4*i+2], h1.x);
            fma2(e2, wr2[4*i+3], h1.y);
        }
#pragma unroll
        for (int i = 0; i < 6; i++){                    // pairs 40..63, H2[20..31]
            ulonglong2 w0 = wsu2[(2*i)*512 + tid];
            ulonglong2 w1 = wsu2[(2*i+1)*512 + tid];
            ulonglong2 h0 = H2[20+2*i], h1 = H2[21+2*i];
            fma2(a2, w0.x, h0.x);
            fma2(c2, w0.y, h0.y);
            fma2(d2, w1.x, h1.x);
            fma2(e2, w1.y, h1.y);
        }
        float a0,a1,b0,b1,d0,d1,e0,e1;
        asm("mov.b64 {%0,%1}, %2;" : "=f"(a0), "=f"(a1) : "l"(a2));
        asm("mov.b64 {%0,%1}, %2;" : "=f"(b0), "=f"(b1) : "l"(c2));
        asm("mov.b64 {%0,%1}, %2;" : "=f"(d0), "=f"(d1) : "l"(d2));
        asm("mov.b64 {%0,%1}, %2;" : "=f"(e0), "=f"(e1) : "l"(e2));
        gs[tid] = xcur + ((a0+a1) + (b0+b1)) + ((d0+d1) + (e0+e1));
        __syncthreads();
        if (tid < HD){
            float ii = sigmoidf_(gs[tid]);
            float ff = sigmoidf_(gs[HD+tid]);
            float gg = tanhf(gs[2*HD+tid]);
            float oo = sigmoidf_(gs[3*HD+tid]);
            c = ff*c + ii*gg;
            hs[tid] = oo*tanhf(c);
        }
        __syncthreads();
        xcur = xnext;
    }
    if (tid < 2*ZD){
        int o = tid & 63;
        const float* W = (tid < ZD) ? (muW + o*HD) : (lvW + o*HD);
        float acc = (tid < ZD) ? mub[o] : lvb[o];
        for (int k = 0; k < HD; k++) acc += W[k]*hs[k];
        acc = leakyf_(acc, 0.1f);
        if (tid < ZD) mu_s[o] = acc;
        else          lv_s[o] = fminf(10.f, fmaxf(-10.f, acc));
    }
    __syncthreads();
    if (tid < ZD){
        float m = mu_s[tid], lv = lv_s[tid];
        out[BB*TT*9 + b*ZD + tid] = m;
        out[BB*TT*9 + BB*ZD + b*ZD + tid] = lv;
        emb[tid] = m + eps[b*ZD + tid]*expf(0.5f*lv);
    }
    __syncthreads();
    if (tid < XD){
        float acc = fcb[tid];
        const float* W = fcW + tid*ZD;
        for (int k = 0; k < ZD; k++) acc += W[k]*emb[k];
        xs[tid] = acc;
    }
    __syncthreads();
    for (int g = tid; g < GG; g += 512){
        float acc = gbih[g];
        const float* W = gWih + (size_t)g*GH;
        for (int k = 0; k < XD; k++) acc += W[k]*xs[k];
        g_gxbase[(size_t)b*GG + g] = acc;
    }
}

// K5: GRU scan + pipelined jf head. 928 threads, 2 batches/block (R12 exact).
__global__ void __launch_bounds__(928) k_gru(
    const float* __restrict__ noise_eps,
    const float* __restrict__ gWih, const float* __restrict__ gWhh,
    const float* __restrict__ gbhh,
    const float* __restrict__ b1,
    const float* __restrict__ W2, const float* __restrict__ b2,
    float* __restrict__ out)
{
    extern __shared__ float sm[];
    ulonglong2* wsA = (ulonglong2*)sm;   // [16][784]: k=32..95 pair-pairs
    float* hb0  = sm + 50176;            // 264 (zero-padded)
    float* hb1  = hb0 + 264;
    float* sums = hb1 + 264;             // [2][784]
    float* ghn  = sums + 2*784;          // [2][264]
    float* f1s  = ghn + 2*264;           // [2][64]
    float* nsAll= f1s + 128;             // [TT][8]
    int tid = threadIdx.x;
    int b0 = blockIdx.x*2;

    for (int j = tid; j < 528; j += 928) hb0[j] = 0.f;
    for (int j = tid; j < TT*8; j += 928){
        int t = j >> 3, r = j & 7, bb = r >> 2, jj = r & 3;
        nsAll[j] = noise_eps[t*(BB*4) + (b0+bb)*4 + jj] * 0.1f;
    }

    unsigned long long wr2[16];
    float w260=0,wn0=0,wn1=0,wn2=0,wn3=0,wt=0,bh=0,gx0b=0,gx1b=0;
    if (tid < GG){
        const float* row = gWhh + (size_t)tid*GH;
#pragma unroll
        for (int i = 0; i < 16; i++)
            asm("mov.b64 %0, {%1,%2};" : "=l"(wr2[i]) : "f"(row[2*i]), "f"(row[2*i+1]));
#pragma unroll
        for (int i = 0; i < 16; i++){
            ulonglong2 w;
            asm("mov.b64 %0, {%1,%2};" : "=l"(w.x) : "f"(row[32+4*i]), "f"(row[33+4*i]));
            asm("mov.b64 %0, {%1,%2};" : "=l"(w.y) : "f"(row[34+4*i]), "f"(row[35+4*i]));
            wsA[i*784 + tid] = w;
        }
        w260 = row[260];
        const float* Wi = gWih + (size_t)tid*GH;
        wn0=Wi[256]; wn1=Wi[257]; wn2=Wi[258]; wn3=Wi[259]; wt=Wi[260];
        bh = gbhh[tid];
        gx0b = g_gxbase[b0*GG + tid];
        gx1b = g_gxbase[(b0+1)*GG + tid];
    }
    __syncthreads();
    const float inv = 1.0f/(float)(TT-1);
    for (int t = 0; t <= TT; t++){
        if (t < TT && tid < GG){
            const float* nsp = nsAll + t*8;
            float tv = (float)t * inv;
            float gx0 = gx0b + wn0*nsp[0]+wn1*nsp[1]+wn2*nsp[2]+wn3*nsp[3] + wt*tv;
            float gx1 = gx1b + wn0*nsp[4]+wn1*nsp[5]+wn2*nsp[6]+wn3*nsp[7] + wt*tv;
            unsigned long long a0p = 0ull, a1p = 0ull;
            const ulonglong2* H0 = (const ulonglong2*)hb0;
            const ulonglong2* H1 = (const ulonglong2*)hb1;
#pragma unroll
            for (int i = 0; i < 8; i++){
                ulonglong2 h0 = H0[i], h1 = H1[i];
                fma2(a0p, wr2[2*i],   h0.x);  fma2(a1p, wr2[2*i],   h1.x);
                fma2(a0p, wr2[2*i+1], h0.y);  fma2(a1p, wr2[2*i+1], h1.y);
            }
#pragma unroll
            for (int i = 0; i < 16; i++){
                ulonglong2 w = wsA[i*784 + tid];
                ulonglong2 h0 = H0[8+i], h1 = H1[8+i];
                fma2(a0p, w.x, h0.x);  fma2(a1p, w.x, h1.x);
                fma2(a0p, w.y, h0.y);  fma2(a1p, w.y, h1.y);
            }
            const ulonglong2* wp = (const ulonglong2*)g_gWhh4 + tid;
#pragma unroll 8
            for (int p = 0; p < 41; p++){
                ulonglong2 w = wp[(size_t)p*GG];
                ulonglong2 h0 = H0[24+p], h1 = H1[24+p];
                fma2(a0p, w.x, h0.x);  fma2(a1p, w.x, h1.x);
                fma2(a0p, w.y, h0.y);  fma2(a1p, w.y, h1.y);
            }
            float s00,s01,s10,s11;
            asm("mov.b64 {%0,%1}, %2;" : "=f"(s00), "=f"(s01) : "l"(a0p));
            asm("mov.b64 {%0,%1}, %2;" : "=f"(s10), "=f"(s11) : "l"(a1p));
            float gh0 = bh + (s00+s01) + w260*hb0[260];
            float gh1 = bh + (s10+s11) + w260*hb1[260];
            float v0 = gx0 + gh0, v1 = gx1 + gh1;
            if (tid >= 522){
                v0 = gx0; v1 = gx1;
                ghn[tid-522] = gh0; ghn[264 + tid-522] = gh1;
            }
            sums[tid] = v0; sums[784 + tid] = v1;
        }
        if (t >= 1 && tid >= 800){
            int q = tid - 800, bb = q >> 6, o = q & 63;
            const float4* hv = (const float4*)(bb ? hb1 : hb0);
            const float4* Wv = g_W1T4 + o;
            float acc = b1[o];
#pragma unroll
            for (int p = 0; p < 66; p++){
                float4 w = Wv[p*ZD];
                float4 h = hv[p];
                acc += w.x*h.x + w.y*h.y + w.z*h.z + w.w*h.w;
            }
            f1s[bb*64 + o] = leakyf_(acc, 0.2f);
        }
        __syncthreads();
        if (t < TT && tid < 522){
            int bb = tid/261, j = tid - bb*261;
            float* hb = bb ? hb1 : hb0;
            const float* s = sums + bb*784;
            float r = sigmoidf_(s[j]);
            float z = sigmoidf_(s[261+j]);
            float n = tanhf(s[522+j] + r*ghn[bb*264 + j]);
            hb[j] = (1.f - z)*n + z*hb[j];
        }
        if (t >= 1 && tid >= 800 && tid < 818){
            int q = tid - 800, bb = q/9, i = q - bb*9;
            float acc = b2[i];
            const float* W = W2 + i*ZD;
            for (int o = 0; o < ZD; o++) acc += W[o]*f1s[bb*64 + o];
            out[(size_t)(b0+bb)*(TT*9) + (t-1)*9 + i] = sigmoidf_(acc);
        }
        __syncthreads();
    }
}

extern "C" void kernel_launch(void* const* d_in, const int* in_sizes, int n_in,
                              void* d_out, int out_size)
{
    const float* input_data = (const float*)d_in[0];
    const float* eps        = (const float*)d_in[1];
    const float* noise_eps  = (const float*)d_in[2];
    const float* proj_W     = (const float*)d_in[3];
    const float* proj_b     = (const float*)d_in[4];
    const float* lstm_Wih   = (const float*)d_in[5];
    const float* lstm_Whh   = (const float*)d_in[6];
    const float* lstm_bih   = (const float*)d_in[7];
    const float* lstm_bhh   = (const float*)d_in[8];
    const float* mu_W       = (const float*)d_in[9];
    const float* mu_b       = (const float*)d_in[10];
    const float* lv_W       = (const float*)d_in[11];
    const float* lv_b       = (const float*)d_in[12];
    const float* fcin_W     = (const float*)d_in[13];
    const float* fcin_b     = (const float*)d_in[14];
    const float* gru_Wih    = (const float*)d_in[15];
    const float* gru_Whh    = (const float*)d_in[16];
    const float* gru_bih    = (const float*)d_in[17];
    const float* gru_bhh    = (const float*)d_in[18];
    const float* jf_W1      = (const float*)d_in[19];
    const float* jf_b1      = (const float*)d_in[20];
    const float* jf_W2      = (const float*)d_in[21];
    const float* jf_b2      = (const float*)d_in[22];
    float* out = (float*)d_out;

    int gemm_smem = 2*2*128*SMSH*2;
    int lstm_smem = 24576*4 + (128 + 512 + 64 + 64 + 64 + 256)*4;
    int gru_smem  = (50176 + 264 + 264 + 2*784 + 2*264 + 128 + TT*8)*4;
    cudaFuncSetAttribute(k_gemm, cudaFuncAttributeMaxDynamicSharedMemorySize, gemm_smem);
    cudaFuncSetAttribute(k_lstm, cudaFuncAttributeMaxDynamicSharedMemorySize, lstm_smem);
    cudaFuncSetAttribute(k_gru,  cudaFuncAttributeMaxDynamicSharedMemorySize, gru_smem);

    k_proj<<<1760, 512>>>(input_data, proj_W, proj_b,
                          lstm_Wih, gru_Whh, jf_W1);
    dim3 g2(HG/128, TT*BB/128);   // (4, 100)
    k_gemm<<<g2, 256, gemm_smem>>>(lstm_bih, lstm_bhh);
    k_lstm<<<BB, 512, lstm_smem>>>(lstm_Whh, eps, mu_W, mu_b, lv_W, lv_b,
                                   fcin_W, fcin_b, gru_Wih, gru_bih, out);
    k_gru<<<BB/2, 928, gru_smem>>>(noise_eps, gru_Wih, gru_Whh, gru_bhh,
                                   jf_b1, jf_W2, jf_b2, out);
}

// round 15
// speedup vs baseline: 1.0776x; 1.0099x over previous
#include <cuda_runtime.h>
#include <cuda_fp16.h>
#include <math.h>
#include <stdint.h>

#define BB 128
#define TT 100
#define PD 4096
#define HG 512
#define HD 128
#define GH 261
#define GG 783
#define ZD 64
#define XD 256

__device__ __half g_projh[BB*TT*PD];
__device__ __half g_Wih16[HG*PD];
__device__ float g_xg[TT*BB*HG];
__device__ float4 g_gWhh4[41*GG];      // gru Whh k=96..259: [p][g]
__device__ float4 g_W1T4[66*ZD];
__device__ float g_gxbase[BB*GG];

__device__ __forceinline__ float sigmoidf_(float x){ return 1.0f/(1.0f+expf(-x)); }
__device__ __forceinline__ float leakyf_(float x, float s){ return x >= 0.0f ? x : s*x; }
__device__ __forceinline__ void fma2(unsigned long long& a, unsigned long long w, unsigned long long h){
    asm("fma.rn.f32x2 %0, %1, %2, %0;" : "+l"(a) : "l"(w), "l"(h));
}
__device__ __forceinline__ void cp16(void* s, const void* g){
    unsigned ss = (unsigned)__cvta_generic_to_shared(s);
    asm volatile("cp.async.cg.shared.global [%0], [%1], 16;\n" :: "r"(ss), "l"(g));
}
#define MMA_F16(c, au, bu) \
  asm volatile("mma.sync.aligned.m16n8k16.row.col.f32.f16.f16.f32 " \
    "{%0,%1,%2,%3},{%4,%5,%6,%7},{%8,%9},{%0,%1,%2,%3};\n" \
    : "+f"(c[0]),"+f"(c[1]),"+f"(c[2]),"+f"(c[3]) \
    : "r"(au[0]),"r"(au[1]),"r"(au[2]),"r"(au[3]),"r"(bu[0]),"r"(bu[1]))

// K1: proj (blocks 0..1599) + weight prep (blocks 1600..1759), fused.
__global__ void __launch_bounds__(512) k_proj(const float* __restrict__ pose,
                                              const float* __restrict__ W,
                                              const float* __restrict__ bias,
                                              const float* __restrict__ Wih,
                                              const float* __restrict__ gWhh,
                                              const float* __restrict__ W1)
{
    int tid = threadIdx.x;
    if (blockIdx.x >= 1600){
        int i0 = (blockIdx.x - 1600)*512 + tid;
        int st = 160*512;
        for (int i = i0; i < HG*PD; i += st)
            g_Wih16[i] = __float2half_rn(Wih[i]);
        for (int i = i0; i < 41*GG; i += st){
            int p = i / GG, g = i - p*GG;
            const float* r = gWhh + (size_t)g*GH + 96 + 4*p;
            g_gWhh4[i] = make_float4(r[0], r[1], r[2], r[3]);
        }
        for (int i = i0; i < 66*ZD; i += st){
            int p = i >> 6, o = i & 63;
            const float* r = W1 + (size_t)o*GH;
            int k = 4*p;
            float4 v;
            v.x = (k   < GH) ? r[k]   : 0.f;
            v.y = (k+1 < GH) ? r[k+1] : 0.f;
            v.z = (k+2 < GH) ? r[k+2] : 0.f;
            v.w = (k+3 < GH) ? r[k+3] : 0.f;
            g_W1T4[i] = v;
        }
        return;
    }
    __shared__ float p[8][9];
    int r0 = blockIdx.x*8;
    if (tid < 72) p[tid/9][tid%9] = pose[r0*9 + tid];
    __syncthreads();
#pragma unroll
    for (int i = 0; i < 8; i++){
        int k = tid + i*512;
        const float* w = W + k*9;
        float wv[9];
#pragma unroll
        for (int j = 0; j < 9; j++) wv[j] = w[j];
        float bk = bias[k];
#pragma unroll
        for (int r = 0; r < 8; r++){
            float acc = bk;
#pragma unroll
            for (int j = 0; j < 9; j++) acc += wv[j]*p[r][j];
            g_projh[(size_t)(r0+r)*PD + k] = __float2half_rn(leakyf_(acc, 0.1f));
        }
    }
}

// K2: fp16 mma.sync GEMM (at packed-fp16 pipe roofline; unchanged)
#define SMSH 72
#define KC 64
__global__ void __launch_bounds__(256, 2) k_gemm(const float* __restrict__ bih,
                                                 const float* __restrict__ bhh)
{
    extern __shared__ __align__(16) char smc[];
    __half* Ash = (__half*)smc;
    __half* Bsh = (__half*)(smc + 2*128*SMSH*2);
    int tid = threadIdx.x, lane = tid & 31, warp = tid >> 5;
    int bn = blockIdx.x, bm = blockIdx.y;
    const __half* Ag = g_projh + (size_t)bm*128*PD;
    const __half* Bg = g_Wih16 + (size_t)bn*128*PD;
    int wm = warp >> 2, wn = warp & 3;
    float acc[4][4][4];
#pragma unroll
    for (int a = 0; a < 4; a++)
#pragma unroll
        for (int b = 0; b < 4; b++)
#pragma unroll
            for (int c = 0; c < 4; c++) acc[a][b][c] = 0.f;

    for (int i = tid; i < 1024; i += 256){
        int row = i >> 3, sub = i & 7;
        cp16(Ash + row*SMSH + sub*8, Ag + (size_t)row*PD + sub*8);
    }
    for (int i = tid; i < 1024; i += 256){
        int row = i >> 3, sub = i & 7;
        cp16(Bsh + row*SMSH + sub*8, Bg + (size_t)row*PD + sub*8);
    }
    asm volatile("cp.async.commit_group;\n");

    for (int c = 0; c < PD/KC; c++){
        int buf = c & 1;
        if (c+1 < PD/KC){
            int nb = buf^1;
            int kof = (c+1)*KC;
            for (int i = tid; i < 1024; i += 256){
                int row = i >> 3, sub = i & 7;
                cp16(Ash + nb*128*SMSH + row*SMSH + sub*8, Ag + (size_t)row*PD + kof + sub*8);
            }
            for (int i = tid; i < 1024; i += 256){
                int row = i >> 3, sub = i & 7;
                cp16(Bsh + nb*128*SMSH + row*SMSH + sub*8, Bg + (size_t)row*PD + kof + sub*8);
            }
        }
        asm volatile("cp.async.commit_group;\n");
        asm volatile("cp.async.wait_group 1;\n");
        __syncthreads();
        const uint32_t* A = (const uint32_t*)(Ash + buf*128*SMSH);
        const uint32_t* B = (const uint32_t*)(Bsh + buf*128*SMSH);
#pragma unroll
        for (int kk = 0; kk < 4; kk++){
            int kw = kk*8 + (lane & 3);
            uint32_t au[4][4], bu[4][2];
#pragma unroll
            for (int mt = 0; mt < 4; mt++){
                int r = wm*64 + mt*16 + (lane>>2);
                au[mt][0] = A[r*36 + kw];
                au[mt][1] = A[(r+8)*36 + kw];
                au[mt][2] = A[r*36 + kw + 4];
                au[mt][3] = A[(r+8)*36 + kw + 4];
            }
#pragma unroll
            for (int nt = 0; nt < 4; nt++){
                int n = wn*32 + nt*8 + (lane>>2);
                bu[nt][0] = B[n*36 + kw];
                bu[nt][1] = B[n*36 + kw + 4];
            }
#pragma unroll
            for (int mt = 0; mt < 4; mt++)
#pragma unroll
                for (int nt = 0; nt < 4; nt++)
                    MMA_F16(acc[mt][nt], au[mt], bu[nt]);
        }
        __syncthreads();
    }
#pragma unroll
    for (int mt = 0; mt < 4; mt++){
#pragma unroll
        for (int nt = 0; nt < 4; nt++){
            int col = bn*128 + wn*32 + nt*8 + (lane&3)*2;
            float bs0 = bih[col]   + bhh[col];
            float bs1 = bih[col+1] + bhh[col+1];
            int r0 = bm*128 + wm*64 + mt*16 + (lane>>2);
            int b0i = r0/TT, t0 = r0 - b0i*TT;
            *(float2*)(g_xg + (size_t)t0*(BB*HG) + b0i*HG + col) =
                make_float2(acc[mt][nt][0]+bs0, acc[mt][nt][1]+bs1);
            int r1 = r0 + 8;
            int b1i = r1/TT, t1 = r1 - b1i*TT;
            *(float2*)(g_xg + (size_t)t1*(BB*HG) + b1i*HG + col) =
                make_float2(acc[mt][nt][2]+bs0, acc[mt][nt][3]+bs1);
        }
    }
}

// K3: LSTM scan nb=1 + fused head; weight split 44 reg-pairs / 20 smem-pairs
__global__ void __launch_bounds__(512) k_lstm(
    const float* __restrict__ Whh,
    const float* __restrict__ eps,
    const float* __restrict__ muW, const float* __restrict__ mub,
    const float* __restrict__ lvW, const float* __restrict__ lvb,
    const float* __restrict__ fcW, const float* __restrict__ fcb,
    const float* __restrict__ gWih, const float* __restrict__ gbih,
    float* __restrict__ out)
{
    extern __shared__ float sm[];
    ulonglong2* wsu2 = (ulonglong2*)sm;          // [10][512]: k=88..127
    float* hs = sm + 20480;                      // 128
    float* gs = hs + 128;                        // 512
    float* mu_s = gs + 512;                      // 64
    float* lv_s = mu_s + 64;                     // 64
    float* emb  = lv_s + 64;                     // 64
    float* xs   = emb + 64;                      // 256
    int tid = threadIdx.x, b = blockIdx.x;

    const ulonglong2* wrow = (const ulonglong2*)(Whh + (size_t)tid*HD);
    unsigned long long wr2[44];                  // pairs 0..43 (k=0..87)
#pragma unroll
    for (int i = 0; i < 22; i++){
        ulonglong2 v = wrow[i];
        wr2[2*i] = v.x; wr2[2*i+1] = v.y;
    }
#pragma unroll
    for (int i = 0; i < 10; i++) wsu2[i*512 + tid] = wrow[22+i];
    if (tid < HD) hs[tid] = 0.f;
    float c = 0.f;
    __syncthreads();
    const float* xg = g_xg + b*HG + tid;
    float xcur = xg[0];
    for (int t = 0; t < TT; t++){
        float xnext = (t < TT-1) ? xg[(size_t)(t+1)*(BB*HG)] : 0.f;
        const ulonglong2* H2 = (const ulonglong2*)hs;   // 32 entries
        unsigned long long a2 = 0ull, c2 = 0ull, d2 = 0ull, e2 = 0ull;
#pragma unroll
        for (int i = 0; i < 11; i++){                   // pairs 0..43, H2[0..21]
            ulonglong2 h0 = H2[2*i], h1 = H2[2*i+1];
            fma2(a2, wr2[4*i],   h0.x);
            fma2(c2, wr2[4*i+1], h0.y);
            fma2(d2, wr2[4*i+2], h1.x);
            fma2(e2, wr2[4*i+3], h1.y);
        }
#pragma unroll
        for (int i = 0; i < 5; i++){                    // pairs 44..63, H2[22..31]
            ulonglong2 w0 = wsu2[(2*i)*512 + tid];
            ulonglong2 w1 = wsu2[(2*i+1)*512 + tid];
            ulonglong2 h0 = H2[22+2*i], h1 = H2[23+2*i];
            fma2(a2, w0.x, h0.x);
            fma2(c2, w0.y, h0.y);
            fma2(d2, w1.x, h1.x);
            fma2(e2, w1.y, h1.y);
        }
        float a0,a1,b0,b1,d0,d1,e0,e1;
        asm("mov.b64 {%0,%1}, %2;" : "=f"(a0), "=f"(a1) : "l"(a2));
        asm("mov.b64 {%0,%1}, %2;" : "=f"(b0), "=f"(b1) : "l"(c2));
        asm("mov.b64 {%0,%1}, %2;" : "=f"(d0), "=f"(d1) : "l"(d2));
        asm("mov.b64 {%0,%1}, %2;" : "=f"(e0), "=f"(e1) : "l"(e2));
        gs[tid] = xcur + ((a0+a1) + (b0+b1)) + ((d0+d1) + (e0+e1));
        __syncthreads();
        if (tid < HD){
            float ii = sigmoidf_(gs[tid]);
            float ff = sigmoidf_(gs[HD+tid]);
            float gg = tanhf(gs[2*HD+tid]);
            float oo = sigmoidf_(gs[3*HD+tid]);
            c = ff*c + ii*gg;
            hs[tid] = oo*tanhf(c);
        }
        __syncthreads();
        xcur = xnext;
    }
    if (tid < 2*ZD){
        int o = tid & 63;
        const float* W = (tid < ZD) ? (muW + o*HD) : (lvW + o*HD);
        float acc = (tid < ZD) ? mub[o] : lvb[o];
        for (int k = 0; k < HD; k++) acc += W[k]*hs[k];
        acc = leakyf_(acc, 0.1f);
        if (tid < ZD) mu_s[o] = acc;
        else          lv_s[o] = fminf(10.f, fmaxf(-10.f, acc));
    }
    __syncthreads();
    if (tid < ZD){
        float m = mu_s[tid], lv = lv_s[tid];
        out[BB*TT*9 + b*ZD + tid] = m;
        out[BB*TT*9 + BB*ZD + b*ZD + tid] = lv;
        emb[tid] = m + eps[b*ZD + tid]*expf(0.5f*lv);
    }
    __syncthreads();
    if (tid < XD){
        float acc = fcb[tid];
        const float* W = fcW + tid*ZD;
        for (int k = 0; k < ZD; k++) acc += W[k]*emb[k];
        xs[tid] = acc;
    }
    __syncthreads();
    for (int g = tid; g < GG; g += 512){
        float acc = gbih[g];
        const float* W = gWih + (size_t)g*GH;
        for (int k = 0; k < XD; k++) acc += W[k]*xs[k];
        g_gxbase[(size_t)b*GG + g] = acc;
    }
}

// K5: GRU scan + pipelined jf head. 928 threads, 2 batches/block.
// Tail loads interleaved with smem FMAs (separate accumulators) for latency cover.
__global__ void __launch_bounds__(928) k_gru(
    const float* __restrict__ noise_eps,
    const float* __restrict__ gWih, const float* __restrict__ gWhh,
    const float* __restrict__ gbhh,
    const float* __restrict__ b1,
    const float* __restrict__ W2, const float* __restrict__ b2,
    float* __restrict__ out)
{
    extern __shared__ float sm[];
    ulonglong2* wsA = (ulonglong2*)sm;   // [16][784]: k=32..95 pair-pairs
    float* hb0  = sm + 50176;
    float* hb1  = hb0 + 264;
    float* sums = hb1 + 264;             // [2][784]
    float* ghn  = sums + 2*784;          // [2][264]
    float* f1s  = ghn + 2*264;           // [2][64]
    float* nsAll= f1s + 128;             // [TT][8]
    int tid = threadIdx.x;
    int b0 = blockIdx.x*2;

    for (int j = tid; j < 528; j += 928) hb0[j] = 0.f;
    for (int j = tid; j < TT*8; j += 928){
        int t = j >> 3, r = j & 7, bb = r >> 2, jj = r & 3;
        nsAll[j] = noise_eps[t*(BB*4) + (b0+bb)*4 + jj] * 0.1f;
    }

    unsigned long long wr2[16];
    float w260=0,wn0=0,wn1=0,wn2=0,wn3=0,wt=0,bh=0,gx0b=0,gx1b=0;
    if (tid < GG){
        const float* row = gWhh + (size_t)tid*GH;
#pragma unroll
        for (int i = 0; i < 16; i++)
            asm("mov.b64 %0, {%1,%2};" : "=l"(wr2[i]) : "f"(row[2*i]), "f"(row[2*i+1]));
#pragma unroll
        for (int i = 0; i < 16; i++){
            ulonglong2 w;
            asm("mov.b64 %0, {%1,%2};" : "=l"(w.x) : "f"(row[32+4*i]), "f"(row[33+4*i]));
            asm("mov.b64 %0, {%1,%2};" : "=l"(w.y) : "f"(row[34+4*i]), "f"(row[35+4*i]));
            wsA[i*784 + tid] = w;
        }
        w260 = row[260];
        const float* Wi = gWih + (size_t)tid*GH;
        wn0=Wi[256]; wn1=Wi[257]; wn2=Wi[258]; wn3=Wi[259]; wt=Wi[260];
        bh = gbhh[tid];
        gx0b = g_gxbase[b0*GG + tid];
        gx1b = g_gxbase[(b0+1)*GG + tid];
    }
    __syncthreads();
    const float inv = 1.0f/(float)(TT-1);
    for (int t = 0; t <= TT; t++){
        if (t < TT && tid < GG){
            const float* nsp = nsAll + t*8;
            float tv = (float)t * inv;
            float gx0 = gx0b + wn0*nsp[0]+wn1*nsp[1]+wn2*nsp[2]+wn3*nsp[3] + wt*tv;
            float gx1 = gx1b + wn0*nsp[4]+wn1*nsp[5]+wn2*nsp[6]+wn3*nsp[7] + wt*tv;
            unsigned long long a0p = 0ull, a1p = 0ull;   // reg+smem accs
            unsigned long long t0p = 0ull, t1p = 0ull;   // tail accs
            const ulonglong2* H0 = (const ulonglong2*)hb0;
            const ulonglong2* H1 = (const ulonglong2*)hb1;
            const ulonglong2* wp = (const ulonglong2*)g_gWhh4 + tid;
            // reg pairs k=0..31
#pragma unroll
            for (int i = 0; i < 8; i++){
                ulonglong2 h0 = H0[i], h1 = H1[i];
                fma2(a0p, wr2[2*i],   h0.x);  fma2(a1p, wr2[2*i],   h1.x);
                fma2(a0p, wr2[2*i+1], h0.y);  fma2(a1p, wr2[2*i+1], h1.y);
            }
            // interleaved: smem iter i with tail packs 2i, 2i+1
#pragma unroll 4
            for (int i = 0; i < 16; i++){
                ulonglong2 wt0 = wp[(size_t)(2*i)*GG];
                ulonglong2 wt1 = wp[(size_t)(2*i+1)*GG];
                ulonglong2 w = wsA[i*784 + tid];
                ulonglong2 h0 = H0[8+i], h1 = H1[8+i];
                fma2(a0p, w.x, h0.x);  fma2(a1p, w.x, h1.x);
                fma2(a0p, w.y, h0.y);  fma2(a1p, w.y, h1.y);
                ulonglong2 th0a = H0[24+2*i], th1a = H1[24+2*i];
                ulonglong2 th0b = H0[25+2*i], th1b = H1[25+2*i];
                fma2(t0p, wt0.x, th0a.x);  fma2(t1p, wt0.x, th1a.x);
                fma2(t0p, wt0.y, th0a.y);  fma2(t1p, wt0.y, th1a.y);
                fma2(t0p, wt1.x, th0b.x);  fma2(t1p, wt1.x, th1b.x);
                fma2(t0p, wt1.y, th0b.y);  fma2(t1p, wt1.y, th1b.y);
            }
            // remaining tail packs 32..40
#pragma unroll 3
            for (int p = 32; p < 41; p++){
                ulonglong2 w = wp[(size_t)p*GG];
                ulonglong2 h0 = H0[24+p], h1 = H1[24+p];
                fma2(t0p, w.x, h0.x);  fma2(t1p, w.x, h1.x);
                fma2(t0p, w.y, h0.y);  fma2(t1p, w.y, h1.y);
            }
            float s00,s01,s10,s11,u00,u01,u10,u11;
            asm("mov.b64 {%0,%1}, %2;" : "=f"(s00), "=f"(s01) : "l"(a0p));
            asm("mov.b64 {%0,%1}, %2;" : "=f"(s10), "=f"(s11) : "l"(a1p));
            asm("mov.b64 {%0,%1}, %2;" : "=f"(u00), "=f"(u01) : "l"(t0p));
            asm("mov.b64 {%0,%1}, %2;" : "=f"(u10), "=f"(u11) : "l"(t1p));
            float gh0 = bh + ((s00+s01) + (u00+u01)) + w260*hb0[260];
            float gh1 = bh + ((s10+s11) + (u10+u11)) + w260*hb1[260];
            float v0 = gx0 + gh0, v1 = gx1 + gh1;
            if (tid >= 522){
                v0 = gx0; v1 = gx1;
                ghn[tid-522] = gh0; ghn[264 + tid-522] = gh1;
            }
            sums[tid] = v0; sums[784 + tid] = v1;
        }
        if (t >= 1 && tid >= 800){
            int q = tid - 800, bb = q >> 6, o = q & 63;
            const float4* hv = (const float4*)(bb ? hb1 : hb0);
            const float4* Wv = g_W1T4 + o;
            float acc = b1[o];
#pragma unroll
            for (int p = 0; p < 66; p++){
                float4 w = Wv[p*ZD];
                float4 h = hv[p];
                acc += w.x*h.x + w.y*h.y + w.z*h.z + w.w*h.w;
            }
            f1s[bb*64 + o] = leakyf_(acc, 0.2f);
        }
        __syncthreads();
        if (t < TT && tid < 522){
            int bb = tid/261, j = tid - bb*261;
            float* hb = bb ? hb1 : hb0;
            const float* s = sums + bb*784;
            float r = sigmoidf_(s[j]);
            float z = sigmoidf_(s[261+j]);
            float n = tanhf(s[522+j] + r*ghn[bb*264 + j]);
            hb[j] = (1.f - z)*n + z*hb[j];
        }
        if (t >= 1 && tid >= 800 && tid < 818){
            int q = tid - 800, bb = q/9, i = q - bb*9;
            float acc = b2[i];
            const float* W = W2 + i*ZD;
            for (int o = 0; o < ZD; o++) acc += W[o]*f1s[bb*64 + o];
            out[(size_t)(b0+bb)*(TT*9) + (t-1)*9 + i] = sigmoidf_(acc);
        }
        __syncthreads();
    }
}

extern "C" void kernel_launch(void* const* d_in, const int* in_sizes, int n_in,
                              void* d_out, int out_size)
{
    const float* input_data = (const float*)d_in[0];
    const float* eps        = (const float*)d_in[1];
    const float* noise_eps  = (const float*)d_in[2];
    const float* proj_W     = (const float*)d_in[3];
    const float* proj_b     = (const float*)d_in[4];
    const float* lstm_Wih   = (const float*)d_in[5];
    const float* lstm_Whh   = (const float*)d_in[6];
    const float* lstm_bih   = (const float*)d_in[7];
    const float* lstm_bhh   = (const float*)d_in[8];
    const float* mu_W       = (const float*)d_in[9];
    const float* mu_b       = (const float*)d_in[10];
    const float* lv_W       = (const float*)d_in[11];
    const float* lv_b       = (const float*)d_in[12];
    const float* fcin_W     = (const float*)d_in[13];
    const float* fcin_b     = (const float*)d_in[14];
    const float* gru_Wih    = (const float*)d_in[15];
    const float* gru_Whh    = (const float*)d_in[16];
    const float* gru_bih    = (const float*)d_in[17];
    const float* gru_bhh    = (const float*)d_in[18];
    const float* jf_W1      = (const float*)d_in[19];
    const float* jf_b1      = (const float*)d_in[20];
    const float* jf_W2      = (const float*)d_in[21];
    const float* jf_b2      = (const float*)d_in[22];
    float* out = (float*)d_out;

    int gemm_smem = 2*2*128*SMSH*2;
    int lstm_smem = 20480*4 + (128 + 512 + 64 + 64 + 64 + 256)*4;
    int gru_smem  = (50176 + 264 + 264 + 2*784 + 2*264 + 128 + TT*8)*4;
    cudaFuncSetAttribute(k_gemm, cudaFuncAttributeMaxDynamicSharedMemorySize, gemm_smem);
    cudaFuncSetAttribute(k_lstm, cudaFuncAttributeMaxDynamicSharedMemorySize, lstm_smem);
    cudaFuncSetAttribute(k_gru,  cudaFuncAttributeMaxDynamicSharedMemorySize, gru_smem);

    k_proj<<<1760, 512>>>(input_data, proj_W, proj_b,
                          lstm_Wih, gru_Whh, jf_W1);
    dim3 g2(HG/128, TT*BB/128);
    k_gemm<<<g2, 256, gemm_smem>>>(lstm_bih, lstm_bhh);
    k_lstm<<<BB, 512, lstm_smem>>>(lstm_Whh, eps, mu_W, mu_b, lv_W, lv_b,
                                   fcin_W, fcin_b, gru_Wih, gru_bih, out);
    k_gru<<<BB/2, 928, gru_smem>>>(noise_eps, gru_Wih, gru_Whh, gru_bhh,
                                   jf_b1, jf_W2, jf_b2, out);
}

// round 16
// speedup vs baseline: 1.0801x; 1.0023x over previous
#include <cuda_runtime.h>
#include <cuda_fp16.h>
#include <math.h>
#include <stdint.h>

#define BB 128
#define TT 100
#define PD 4096
#define HG 512
#define HD 128
#define GH 261
#define GG 783
#define ZD 64
#define XD 256

__device__ __half g_projh[BB*TT*PD];
__device__ __half g_Wih16[HG*PD];
__device__ float g_xg[TT*BB*HG];
__device__ float4 g_gWhh4[41*GG];      // gru Whh k=96..259: [p][g]
__device__ float4 g_W1T4[66*ZD];
__device__ float g_gxbase[BB*GG];

__device__ __forceinline__ float sigmoidf_(float x){ return 1.0f/(1.0f+expf(-x)); }
__device__ __forceinline__ float leakyf_(float x, float s){ return x >= 0.0f ? x : s*x; }
__device__ __forceinline__ void fma2(unsigned long long& a, unsigned long long w, unsigned long long h){
    asm("fma.rn.f32x2 %0, %1, %2, %0;" : "+l"(a) : "l"(w), "l"(h));
}
__device__ __forceinline__ void cp16(void* s, const void* g){
    unsigned ss = (unsigned)__cvta_generic_to_shared(s);
    asm volatile("cp.async.cg.shared.global [%0], [%1], 16;\n" :: "r"(ss), "l"(g));
}
#define MMA_F16(c, au, bu) \
  asm volatile("mma.sync.aligned.m16n8k16.row.col.f32.f16.f16.f32 " \
    "{%0,%1,%2,%3},{%4,%5,%6,%7},{%8,%9},{%0,%1,%2,%3};\n" \
    : "+f"(c[0]),"+f"(c[1]),"+f"(c[2]),"+f"(c[3]) \
    : "r"(au[0]),"r"(au[1]),"r"(au[2]),"r"(au[3]),"r"(bu[0]),"r"(bu[1]))

// K1: proj (blocks 0..1599) + weight prep (blocks 1600..1759), fused.
__global__ void __launch_bounds__(512) k_proj(const float* __restrict__ pose,
                                              const float* __restrict__ W,
                                              const float* __restrict__ bias,
                                              const float* __restrict__ Wih,
                                              const float* __restrict__ gWhh,
                                              const float* __restrict__ W1)
{
    int tid = threadIdx.x;
    if (blockIdx.x >= 1600){
        int i0 = (blockIdx.x - 1600)*512 + tid;
        int st = 160*512;
        for (int i = i0; i < HG*PD; i += st)
            g_Wih16[i] = __float2half_rn(Wih[i]);
        for (int i = i0; i < 41*GG; i += st){
            int p = i / GG, g = i - p*GG;
            const float* r = gWhh + (size_t)g*GH + 96 + 4*p;
            g_gWhh4[i] = make_float4(r[0], r[1], r[2], r[3]);
        }
        for (int i = i0; i < 66*ZD; i += st){
            int p = i >> 6, o = i & 63;
            const float* r = W1 + (size_t)o*GH;
            int k = 4*p;
            float4 v;
            v.x = (k   < GH) ? r[k]   : 0.f;
            v.y = (k+1 < GH) ? r[k+1] : 0.f;
            v.z = (k+2 < GH) ? r[k+2] : 0.f;
            v.w = (k+3 < GH) ? r[k+3] : 0.f;
            g_W1T4[i] = v;
        }
        return;
    }
    __shared__ float p[8][9];
    int r0 = blockIdx.x*8;
    if (tid < 72) p[tid/9][tid%9] = pose[r0*9 + tid];
    __syncthreads();
#pragma unroll
    for (int i = 0; i < 8; i++){
        int k = tid + i*512;
        const float* w = W + k*9;
        float wv[9];
#pragma unroll
        for (int j = 0; j < 9; j++) wv[j] = w[j];
        float bk = bias[k];
#pragma unroll
        for (int r = 0; r < 8; r++){
            float acc = bk;
#pragma unroll
            for (int j = 0; j < 9; j++) acc += wv[j]*p[r][j];
            g_projh[(size_t)(r0+r)*PD + k] = __float2half_rn(leakyf_(acc, 0.1f));
        }
    }
}

// K2: fp16 mma.sync GEMM (at packed-fp16 pipe roofline; unchanged)
#define SMSH 72
#define KC 64
__global__ void __launch_bounds__(256, 2) k_gemm(const float* __restrict__ bih,
                                                 const float* __restrict__ bhh)
{
    extern __shared__ __align__(16) char smc[];
    __half* Ash = (__half*)smc;
    __half* Bsh = (__half*)(smc + 2*128*SMSH*2);
    int tid = threadIdx.x, lane = tid & 31, warp = tid >> 5;
    int bn = blockIdx.x, bm = blockIdx.y;
    const __half* Ag = g_projh + (size_t)bm*128*PD;
    const __half* Bg = g_Wih16 + (size_t)bn*128*PD;
    int wm = warp >> 2, wn = warp & 3;
    float acc[4][4][4];
#pragma unroll
    for (int a = 0; a < 4; a++)
#pragma unroll
        for (int b = 0; b < 4; b++)
#pragma unroll
            for (int c = 0; c < 4; c++) acc[a][b][c] = 0.f;

    for (int i = tid; i < 1024; i += 256){
        int row = i >> 3, sub = i & 7;
        cp16(Ash + row*SMSH + sub*8, Ag + (size_t)row*PD + sub*8);
    }
    for (int i = tid; i < 1024; i += 256){
        int row = i >> 3, sub = i & 7;
        cp16(Bsh + row*SMSH + sub*8, Bg + (size_t)row*PD + sub*8);
    }
    asm volatile("cp.async.commit_group;\n");

    for (int c = 0; c < PD/KC; c++){
        int buf = c & 1;
        if (c+1 < PD/KC){
            int nb = buf^1;
            int kof = (c+1)*KC;
            for (int i = tid; i < 1024; i += 256){
                int row = i >> 3, sub = i & 7;
                cp16(Ash + nb*128*SMSH + row*SMSH + sub*8, Ag + (size_t)row*PD + kof + sub*8);
            }
            for (int i = tid; i < 1024; i += 256){
                int row = i >> 3, sub = i & 7;
                cp16(Bsh + nb*128*SMSH + row*SMSH + sub*8, Bg + (size_t)row*PD + kof + sub*8);
            }
        }
        asm volatile("cp.async.commit_group;\n");
        asm volatile("cp.async.wait_group 1;\n");
        __syncthreads();
        const uint32_t* A = (const uint32_t*)(Ash + buf*128*SMSH);
        const uint32_t* B = (const uint32_t*)(Bsh + buf*128*SMSH);
#pragma unroll
        for (int kk = 0; kk < 4; kk++){
            int kw = kk*8 + (lane & 3);
            uint32_t au[4][4], bu[4][2];
#pragma unroll
            for (int mt = 0; mt < 4; mt++){
                int r = wm*64 + mt*16 + (lane>>2);
                au[mt][0] = A[r*36 + kw];
                au[mt][1] = A[(r+8)*36 + kw];
                au[mt][2] = A[r*36 + kw + 4];
                au[mt][3] = A[(r+8)*36 + kw + 4];
            }
#pragma unroll
            for (int nt = 0; nt < 4; nt++){
                int n = wn*32 + nt*8 + (lane>>2);
                bu[nt][0] = B[n*36 + kw];
                bu[nt][1] = B[n*36 + kw + 4];
            }
#pragma unroll
            for (int mt = 0; mt < 4; mt++)
#pragma unroll
                for (int nt = 0; nt < 4; nt++)
                    MMA_F16(acc[mt][nt], au[mt], bu[nt]);
        }
        __syncthreads();
    }
#pragma unroll
    for (int mt = 0; mt < 4; mt++){
#pragma unroll
        for (int nt = 0; nt < 4; nt++){
            int col = bn*128 + wn*32 + nt*8 + (lane&3)*2;
            float bs0 = bih[col]   + bhh[col];
            float bs1 = bih[col+1] + bhh[col+1];
            int r0 = bm*128 + wm*64 + mt*16 + (lane>>2);
            int b0i = r0/TT, t0 = r0 - b0i*TT;
            *(float2*)(g_xg + (size_t)t0*(BB*HG) + b0i*HG + col) =
                make_float2(acc[mt][nt][0]+bs0, acc[mt][nt][1]+bs1);
            int r1 = r0 + 8;
            int b1i = r1/TT, t1 = r1 - b1i*TT;
            *(float2*)(g_xg + (size_t)t1*(BB*HG) + b1i*HG + col) =
                make_float2(acc[mt][nt][2]+bs0, acc[mt][nt][3]+bs1);
        }
    }
}

// K3: LSTM scan, gate-interleaved mapping: thread tid -> gate (tid&3), cell (tid>>2).
// One barrier per step; activations parallel across all 512 threads; cell update
// via intra-quad shuffles. Weight split 44 reg-pairs / 20 smem-pairs. Fused head.
__global__ void __launch_bounds__(512) k_lstm(
    const float* __restrict__ Whh,
    const float* __restrict__ eps,
    const float* __restrict__ muW, const float* __restrict__ mub,
    const float* __restrict__ lvW, const float* __restrict__ lvb,
    const float* __restrict__ fcW, const float* __restrict__ fcb,
    const float* __restrict__ gWih, const float* __restrict__ gbih,
    float* __restrict__ out)
{
    extern __shared__ float sm[];
    ulonglong2* wsu2 = (ulonglong2*)sm;          // [10][512]: k=88..127
    float* hs = sm + 20480;                      // 128
    float* mu_s = hs + 128;                      // 64
    float* lv_s = mu_s + 64;                     // 64
    float* emb  = lv_s + 64;                     // 64
    float* xs   = emb + 64;                      // 256
    int tid = threadIdx.x, b = blockIdx.x;
    int gate = tid & 3, cell = tid >> 2;
    int grow = gate*HD + cell;                   // gate row in (i,f,g,o) order

    const ulonglong2* wrow = (const ulonglong2*)(Whh + (size_t)grow*HD);
    unsigned long long wr2[44];                  // pairs 0..43 (k=0..87)
#pragma unroll
    for (int i = 0; i < 22; i++){
        ulonglong2 v = wrow[i];
        wr2[2*i] = v.x; wr2[2*i+1] = v.y;
    }
#pragma unroll
    for (int i = 0; i < 10; i++) wsu2[i*512 + tid] = wrow[22+i];
    if (tid < HD) hs[tid] = 0.f;
    float c = 0.f;                               // live only in gate==1 threads
    __syncthreads();
    const float* xg = g_xg + b*HG + grow;
    float xcur = xg[0];
    for (int t = 0; t < TT; t++){
        float xnext = (t < TT-1) ? xg[(size_t)(t+1)*(BB*HG)] : 0.f;
        const ulonglong2* H2 = (const ulonglong2*)hs;
        unsigned long long a2 = 0ull, c2 = 0ull, d2 = 0ull, e2 = 0ull;
#pragma unroll
        for (int i = 0; i < 11; i++){
            ulonglong2 h0 = H2[2*i], h1 = H2[2*i+1];
            fma2(a2, wr2[4*i],   h0.x);
            fma2(c2, wr2[4*i+1], h0.y);
            fma2(d2, wr2[4*i+2], h1.x);
            fma2(e2, wr2[4*i+3], h1.y);
        }
#pragma unroll
        for (int i = 0; i < 5; i++){
            ulonglong2 w0 = wsu2[(2*i)*512 + tid];
            ulonglong2 w1 = wsu2[(2*i+1)*512 + tid];
            ulonglong2 h0 = H2[22+2*i], h1 = H2[23+2*i];
            fma2(a2, w0.x, h0.x);
            fma2(c2, w0.y, h0.y);
            fma2(d2, w1.x, h1.x);
            fma2(e2, w1.y, h1.y);
        }
        float a0,a1,b0,b1,d0,d1,e0,e1;
        asm("mov.b64 {%0,%1}, %2;" : "=f"(a0), "=f"(a1) : "l"(a2));
        asm("mov.b64 {%0,%1}, %2;" : "=f"(b0), "=f"(b1) : "l"(c2));
        asm("mov.b64 {%0,%1}, %2;" : "=f"(d0), "=f"(d1) : "l"(d2));
        asm("mov.b64 {%0,%1}, %2;" : "=f"(e0), "=f"(e1) : "l"(e2));
        float s = xcur + ((a0+a1) + (b0+b1)) + ((d0+d1) + (e0+e1));
        // parallel activation: tanh for gate 2, sigmoid otherwise
        float v = (gate == 2) ? tanhf(s) : sigmoidf_(s);
        // quad assemble: w = partner(v, xor 2): g0<-g2(g~), g1<-g3(o), g2<-g0(i), g3<-g1(f)
        float w = __shfl_xor_sync(0xffffffffu, v, 2);
        float pr = v * w;                         // at g0: i*g~
        float x1 = __shfl_xor_sync(0xffffffffu, pr, 1);  // g1 <- g0: i*g~
        if (gate == 1){
            c = v*c + x1;                         // f*c + i*g~
            hs[cell] = w * tanhf(c);              // o * tanh(c)
        }
        __syncthreads();
        xcur = xnext;
    }
    if (tid < 2*ZD){
        int o = tid & 63;
        const float* W = (tid < ZD) ? (muW + o*HD) : (lvW + o*HD);
        float acc = (tid < ZD) ? mub[o] : lvb[o];
        for (int k = 0; k < HD; k++) acc += W[k]*hs[k];
        acc = leakyf_(acc, 0.1f);
        if (tid < ZD) mu_s[o] = acc;
        else          lv_s[o] = fminf(10.f, fmaxf(-10.f, acc));
    }
    __syncthreads();
    if (tid < ZD){
        float m = mu_s[tid], lv = lv_s[tid];
        out[BB*TT*9 + b*ZD + tid] = m;
        out[BB*TT*9 + BB*ZD + b*ZD + tid] = lv;
        emb[tid] = m + eps[b*ZD + tid]*expf(0.5f*lv);
    }
    __syncthreads();
    if (tid < XD){
        float acc = fcb[tid];
        const float* W = fcW + tid*ZD;
        for (int k = 0; k < ZD; k++) acc += W[k]*emb[k];
        xs[tid] = acc;
    }
    __syncthreads();
    for (int g = tid; g < GG; g += 512){
        float acc = gbih[g];
        const float* W = gWih + (size_t)g*GH;
        for (int k = 0; k < XD; k++) acc += W[k]*xs[k];
        g_gxbase[(size_t)b*GG + g] = acc;
    }
}

// K5: GRU scan + pipelined jf head. 928 threads, 2 batches/block, tail interleaved.
__global__ void __launch_bounds__(928) k_gru(
    const float* __restrict__ noise_eps,
    const float* __restrict__ gWih, const float* __restrict__ gWhh,
    const float* __restrict__ gbhh,
    const float* __restrict__ b1,
    const float* __restrict__ W2, const float* __restrict__ b2,
    float* __restrict__ out)
{
    extern __shared__ float sm[];
    ulonglong2* wsA = (ulonglong2*)sm;   // [16][784]: k=32..95 pair-pairs
    float* hb0  = sm + 50176;
    float* hb1  = hb0 + 264;
    float* sums = hb1 + 264;             // [2][784]
    float* ghn  = sums + 2*784;          // [2][264]
    float* f1s  = ghn + 2*264;           // [2][64]
    float* nsAll= f1s + 128;             // [TT][8]
    int tid = threadIdx.x;
    int b0 = blockIdx.x*2;

    for (int j = tid; j < 528; j += 928) hb0[j] = 0.f;
    for (int j = tid; j < TT*8; j += 928){
        int t = j >> 3, r = j & 7, bb = r >> 2, jj = r & 3;
        nsAll[j] = noise_eps[t*(BB*4) + (b0+bb)*4 + jj] * 0.1f;
    }

    unsigned long long wr2[16];
    float w260=0,wn0=0,wn1=0,wn2=0,wn3=0,wt=0,bh=0,gx0b=0,gx1b=0;
    if (tid < GG){
        const float* row = gWhh + (size_t)tid*GH;
#pragma unroll
        for (int i = 0; i < 16; i++)
            asm("mov.b64 %0, {%1,%2};" : "=l"(wr2[i]) : "f"(row[2*i]), "f"(row[2*i+1]));
#pragma unroll
        for (int i = 0; i < 16; i++){
            ulonglong2 w;
            asm("mov.b64 %0, {%1,%2};" : "=l"(w.x) : "f"(row[32+4*i]), "f"(row[33+4*i]));
            asm("mov.b64 %0, {%1,%2};" : "=l"(w.y) : "f"(row[34+4*i]), "f"(row[35+4*i]));
            wsA[i*784 + tid] = w;
        }
        w260 = row[260];
        const float* Wi = gWih + (size_t)tid*GH;
        wn0=Wi[256]; wn1=Wi[257]; wn2=Wi[258]; wn3=Wi[259]; wt=Wi[260];
        bh = gbhh[tid];
        gx0b = g_gxbase[b0*GG + tid];
        gx1b = g_gxbase[(b0+1)*GG + tid];
    }
    __syncthreads();
    const float inv = 1.0f/(float)(TT-1);
    for (int t = 0; t <= TT; t++){
        if (t < TT && tid < GG){
            const float* nsp = nsAll + t*8;
            float tv = (float)t * inv;
            float gx0 = gx0b + wn0*nsp[0]+wn1*nsp[1]+wn2*nsp[2]+wn3*nsp[3] + wt*tv;
            float gx1 = gx1b + wn0*nsp[4]+wn1*nsp[5]+wn2*nsp[6]+wn3*nsp[7] + wt*tv;
            unsigned long long a0p = 0ull, a1p = 0ull;
            unsigned long long t0p = 0ull, t1p = 0ull;
            const ulonglong2* H0 = (const ulonglong2*)hb0;
            const ulonglong2* H1 = (const ulonglong2*)hb1;
            const ulonglong2* wp = (const ulonglong2*)g_gWhh4 + tid;
#pragma unroll
            for (int i = 0; i < 8; i++){
                ulonglong2 h0 = H0[i], h1 = H1[i];
                fma2(a0p, wr2[2*i],   h0.x);  fma2(a1p, wr2[2*i],   h1.x);
                fma2(a0p, wr2[2*i+1], h0.y);  fma2(a1p, wr2[2*i+1], h1.y);
            }
#pragma unroll 4
            for (int i = 0; i < 16; i++){
                ulonglong2 wt0 = wp[(size_t)(2*i)*GG];
                ulonglong2 wt1 = wp[(size_t)(2*i+1)*GG];
                ulonglong2 w = wsA[i*784 + tid];
                ulonglong2 h0 = H0[8+i], h1 = H1[8+i];
                fma2(a0p, w.x, h0.x);  fma2(a1p, w.x, h1.x);
                fma2(a0p, w.y, h0.y);  fma2(a1p, w.y, h1.y);
                ulonglong2 th0a = H0[24+2*i], th1a = H1[24+2*i];
                ulonglong2 th0b = H0[25+2*i], th1b = H1[25+2*i];
                fma2(t0p, wt0.x, th0a.x);  fma2(t1p, wt0.x, th1a.x);
                fma2(t0p, wt0.y, th0a.y);  fma2(t1p, wt0.y, th1a.y);
                fma2(t0p, wt1.x, th0b.x);  fma2(t1p, wt1.x, th1b.x);
                fma2(t0p, wt1.y, th0b.y);  fma2(t1p, wt1.y, th1b.y);
            }
#pragma unroll 3
            for (int p = 32; p < 41; p++){
                ulonglong2 w = wp[(size_t)p*GG];
                ulonglong2 h0 = H0[24+p], h1 = H1[24+p];
                fma2(t0p, w.x, h0.x);  fma2(t1p, w.x, h1.x);
                fma2(t0p, w.y, h0.y);  fma2(t1p, w.y, h1.y);
            }
            float s00,s01,s10,s11,u00,u01,u10,u11;
            asm("mov.b64 {%0,%1}, %2;" : "=f"(s00), "=f"(s01) : "l"(a0p));
            asm("mov.b64 {%0,%1}, %2;" : "=f"(s10), "=f"(s11) : "l"(a1p));
            asm("mov.b64 {%0,%1}, %2;" : "=f"(u00), "=f"(u01) : "l"(t0p));
            asm("mov.b64 {%0,%1}, %2;" : "=f"(u10), "=f"(u11) : "l"(t1p));
            float gh0 = bh + ((s00+s01) + (u00+u01)) + w260*hb0[260];
            float gh1 = bh + ((s10+s11) + (u10+u11)) + w260*hb1[260];
            float v0 = gx0 + gh0, v1 = gx1 + gh1;
            if (tid >= 522){
                v0 = gx0; v1 = gx1;
                ghn[tid-522] = gh0; ghn[264 + tid-522] = gh1;
            }
            sums[tid] = v0; sums[784 + tid] = v1;
        }
        if (t >= 1 && tid >= 800){
            int q = tid - 800, bb = q >> 6, o = q & 63;
            const float4* hv = (const float4*)(bb ? hb1 : hb0);
            const float4* Wv = g_W1T4 + o;
            float acc = b1[o];
#pragma unroll
            for (int p = 0; p < 66; p++){
                float4 w = Wv[p*ZD];
                float4 h = hv[p];
                acc += w.x*h.x + w.y*h.y + w.z*h.z + w.w*h.w;
            }
            f1s[bb*64 + o] = leakyf_(acc, 0.2f);
        }
        __syncthreads();
        if (t < TT && tid < 522){
            int bb = tid/261, j = tid - bb*261;
            float* hb = bb ? hb1 : hb0;
            const float* s = sums + bb*784;
            float r = sigmoidf_(s[j]);
            float z = sigmoidf_(s[261+j]);
            float n = tanhf(s[522+j] + r*ghn[bb*264 + j]);
            hb[j] = (1.f - z)*n + z*hb[j];
        }
        if (t >= 1 && tid >= 800 && tid < 818){
            int q = tid - 800, bb = q/9, i = q - bb*9;
            float acc = b2[i];
            const float* W = W2 + i*ZD;
            for (int o = 0; o < ZD; o++) acc += W[o]*f1s[bb*64 + o];
            out[(size_t)(b0+bb)*(TT*9) + (t-1)*9 + i] = sigmoidf_(acc);
        }
        __syncthreads();
    }
}

extern "C" void kernel_launch(void* const* d_in, const int* in_sizes, int n_in,
                              void* d_out, int out_size)
{
    const float* input_data = (const float*)d_in[0];
    const float* eps        = (const float*)d_in[1];
    const float* noise_eps  = (const float*)d_in[2];
    const float* proj_W     = (const float*)d_in[3];
    const float* proj_b     = (const float*)d_in[4];
    const float* lstm_Wih   = (const float*)d_in[5];
    const float* lstm_Whh   = (const float*)d_in[6];
    const float* lstm_bih   = (const float*)d_in[7];
    const float* lstm_bhh   = (const float*)d_in[8];
    const float* mu_W       = (const float*)d_in[9];
    const float* mu_b       = (const float*)d_in[10];
    const float* lv_W       = (const float*)d_in[11];
    const float* lv_b       = (const float*)d_in[12];
    const float* fcin_W     = (const float*)d_in[13];
    const float* fcin_b     = (const float*)d_in[14];
    const float* gru_Wih    = (const float*)d_in[15];
    const float* gru_Whh    = (const float*)d_in[16];
    const float* gru_bih    = (const float*)d_in[17];
    const float* gru_bhh    = (const float*)d_in[18];
    const float* jf_W1      = (const float*)d_in[19];
    const float* jf_b1      = (const float*)d_in[20];
    const float* jf_W2      = (const float*)d_in[21];
    const float* jf_b2      = (const float*)d_in[22];
    float* out = (float*)d_out;

    int gemm_smem = 2*2*128*SMSH*2;
    int lstm_smem = 20480*4 + (128 + 64 + 64 + 64 + 256)*4;
    int gru_smem  = (50176 + 264 + 264 + 2*784 + 2*264 + 128 + TT*8)*4;
    cudaFuncSetAttribute(k_gemm, cudaFuncAttributeMaxDynamicSharedMemorySize, gemm_smem);
    cudaFuncSetAttribute(k_lstm, cudaFuncAttributeMaxDynamicSharedMemorySize, lstm_smem);
    cudaFuncSetAttribute(k_gru,  cudaFuncAttributeMaxDynamicSharedMemorySize, gru_smem);

    k_proj<<<1760, 512>>>(input_data, proj_W, proj_b,
                          lstm_Wih, gru_Whh, jf_W1);
    dim3 g2(HG/128, TT*BB/128);
    k_gemm<<<g2, 256, gemm_smem>>>(lstm_bih, lstm_bhh);
    k_lstm<<<BB, 512, lstm_smem>>>(lstm_Whh, eps, mu_W, mu_b, lv_W, lv_b,
                                   fcin_W, fcin_b, gru_Wih, gru_bih, out);
    k_gru<<<BB/2, 928, gru_smem>>>(noise_eps, gru_Wih, gru_Whh, gru_bhh,
                                   jf_b1, jf_W2, jf_b2, out);
}

// round 17
// speedup vs baseline: 1.0828x; 1.0025x over previous
#include <cuda_runtime.h>
#include <cuda_fp16.h>
#include <math.h>
#include <stdint.h>

#define BB 128
#define TT 100
#define PD 4096
#define HG 512
#define HD 128
#define GH 261
#define GG 783
#define ZD 64
#define XD 256

__device__ __half g_projh[BB*TT*PD];
__device__ __half g_Wih16[HG*PD];
__device__ float g_xg[TT*BB*HG];
__device__ float4 g_gWhh4[41*GG];      // gru Whh k=96..259: [p][g]
__device__ float4 g_W1T4[66*ZD];
__device__ float g_gxbase[BB*GG];

__device__ __forceinline__ float sigmoidf_(float x){ return 1.0f/(1.0f+expf(-x)); }
__device__ __forceinline__ float leakyf_(float x, float s){ return x >= 0.0f ? x : s*x; }
__device__ __forceinline__ void fma2(unsigned long long& a, unsigned long long w, unsigned long long h){
    asm("fma.rn.f32x2 %0, %1, %2, %0;" : "+l"(a) : "l"(w), "l"(h));
}
__device__ __forceinline__ void cp16(void* s, const void* g){
    unsigned ss = (unsigned)__cvta_generic_to_shared(s);
    asm volatile("cp.async.cg.shared.global [%0], [%1], 16;\n" :: "r"(ss), "l"(g));
}
#define MMA_F16(c, au, bu) \
  asm volatile("mma.sync.aligned.m16n8k16.row.col.f32.f16.f16.f32 " \
    "{%0,%1,%2,%3},{%4,%5,%6,%7},{%8,%9},{%0,%1,%2,%3};\n" \
    : "+f"(c[0]),"+f"(c[1]),"+f"(c[2]),"+f"(c[3]) \
    : "r"(au[0]),"r"(au[1]),"r"(au[2]),"r"(au[3]),"r"(bu[0]),"r"(bu[1]))

// K1: proj (blocks 0..1599) + weight prep (blocks 1600..1759), fused.
__global__ void __launch_bounds__(512) k_proj(const float* __restrict__ pose,
                                              const float* __restrict__ W,
                                              const float* __restrict__ bias,
                                              const float* __restrict__ Wih,
                                              const float* __restrict__ gWhh,
                                              const float* __restrict__ W1)
{
    int tid = threadIdx.x;
    if (blockIdx.x >= 1600){
        int i0 = (blockIdx.x - 1600)*512 + tid;
        int st = 160*512;
        for (int i = i0; i < HG*PD; i += st)
            g_Wih16[i] = __float2half_rn(Wih[i]);
        for (int i = i0; i < 41*GG; i += st){
            int p = i / GG, g = i - p*GG;
            const float* r = gWhh + (size_t)g*GH + 96 + 4*p;
            g_gWhh4[i] = make_float4(r[0], r[1], r[2], r[3]);
        }
        for (int i = i0; i < 66*ZD; i += st){
            int p = i >> 6, o = i & 63;
            const float* r = W1 + (size_t)o*GH;
            int k = 4*p;
            float4 v;
            v.x = (k   < GH) ? r[k]   : 0.f;
            v.y = (k+1 < GH) ? r[k+1] : 0.f;
            v.z = (k+2 < GH) ? r[k+2] : 0.f;
            v.w = (k+3 < GH) ? r[k+3] : 0.f;
            g_W1T4[i] = v;
        }
        return;
    }
    __shared__ float p[8][9];
    int r0 = blockIdx.x*8;
    if (tid < 72) p[tid/9][tid%9] = pose[r0*9 + tid];
    __syncthreads();
#pragma unroll
    for (int i = 0; i < 8; i++){
        int k = tid + i*512;
        const float* w = W + k*9;
        float wv[9];
#pragma unroll
        for (int j = 0; j < 9; j++) wv[j] = w[j];
        float bk = bias[k];
#pragma unroll
        for (int r = 0; r < 8; r++){
            float acc = bk;
#pragma unroll
            for (int j = 0; j < 9; j++) acc += wv[j]*p[r][j];
            g_projh[(size_t)(r0+r)*PD + k] = __float2half_rn(leakyf_(acc, 0.1f));
        }
    }
}

// K2: fp16 mma.sync GEMM (at packed-fp16 pipe roofline; unchanged)
#define SMSH 72
#define KC 64
__global__ void __launch_bounds__(256, 2) k_gemm(const float* __restrict__ bih,
                                                 const float* __restrict__ bhh)
{
    extern __shared__ __align__(16) char smc[];
    __half* Ash = (__half*)smc;
    __half* Bsh = (__half*)(smc + 2*128*SMSH*2);
    int tid = threadIdx.x, lane = tid & 31, warp = tid >> 5;
    int bn = blockIdx.x, bm = blockIdx.y;
    const __half* Ag = g_projh + (size_t)bm*128*PD;
    const __half* Bg = g_Wih16 + (size_t)bn*128*PD;
    int wm = warp >> 2, wn = warp & 3;
    float acc[4][4][4];
#pragma unroll
    for (int a = 0; a < 4; a++)
#pragma unroll
        for (int b = 0; b < 4; b++)
#pragma unroll
            for (int c = 0; c < 4; c++) acc[a][b][c] = 0.f;

    for (int i = tid; i < 1024; i += 256){
        int row = i >> 3, sub = i & 7;
        cp16(Ash + row*SMSH + sub*8, Ag + (size_t)row*PD + sub*8);
    }
    for (int i = tid; i < 1024; i += 256){
        int row = i >> 3, sub = i & 7;
        cp16(Bsh + row*SMSH + sub*8, Bg + (size_t)row*PD + sub*8);
    }
    asm volatile("cp.async.commit_group;\n");

    for (int c = 0; c < PD/KC; c++){
        int buf = c & 1;
        if (c+1 < PD/KC){
            int nb = buf^1;
            int kof = (c+1)*KC;
            for (int i = tid; i < 1024; i += 256){
                int row = i >> 3, sub = i & 7;
                cp16(Ash + nb*128*SMSH + row*SMSH + sub*8, Ag + (size_t)row*PD + kof + sub*8);
            }
            for (int i = tid; i < 1024; i += 256){
                int row = i >> 3, sub = i & 7;
                cp16(Bsh + nb*128*SMSH + row*SMSH + sub*8, Bg + (size_t)row*PD + kof + sub*8);
            }
        }
        asm volatile("cp.async.commit_group;\n");
        asm volatile("cp.async.wait_group 1;\n");
        __syncthreads();
        const uint32_t* A = (const uint32_t*)(Ash + buf*128*SMSH);
        const uint32_t* B = (const uint32_t*)(Bsh + buf*128*SMSH);
#pragma unroll
        for (int kk = 0; kk < 4; kk++){
            int kw = kk*8 + (lane & 3);
            uint32_t au[4][4], bu[4][2];
#pragma unroll
            for (int mt = 0; mt < 4; mt++){
                int r = wm*64 + mt*16 + (lane>>2);
                au[mt][0] = A[r*36 + kw];
                au[mt][1] = A[(r+8)*36 + kw];
                au[mt][2] = A[r*36 + kw + 4];
                au[mt][3] = A[(r+8)*36 + kw + 4];
            }
#pragma unroll
            for (int nt = 0; nt < 4; nt++){
                int n = wn*32 + nt*8 + (lane>>2);
                bu[nt][0] = B[n*36 + kw];
                bu[nt][1] = B[n*36 + kw + 4];
            }
#pragma unroll
            for (int mt = 0; mt < 4; mt++)
#pragma unroll
                for (int nt = 0; nt < 4; nt++)
                    MMA_F16(acc[mt][nt], au[mt], bu[nt]);
        }
        __syncthreads();
    }
#pragma unroll
    for (int mt = 0; mt < 4; mt++){
#pragma unroll
        for (int nt = 0; nt < 4; nt++){
            int col = bn*128 + wn*32 + nt*8 + (lane&3)*2;
            float bs0 = bih[col]   + bhh[col];
            float bs1 = bih[col+1] + bhh[col+1];
            int r0 = bm*128 + wm*64 + mt*16 + (lane>>2);
            int b0i = r0/TT, t0 = r0 - b0i*TT;
            *(float2*)(g_xg + (size_t)t0*(BB*HG) + b0i*HG + col) =
                make_float2(acc[mt][nt][0]+bs0, acc[mt][nt][1]+bs1);
            int r1 = r0 + 8;
            int b1i = r1/TT, t1 = r1 - b1i*TT;
            *(float2*)(g_xg + (size_t)t1*(BB*HG) + b1i*HG + col) =
                make_float2(acc[mt][nt][2]+bs0, acc[mt][nt][3]+bs1);
        }
    }
}

// K3: LSTM scan, gate-interleaved (thread -> gate tid&3, cell tid>>2), one
// barrier/step, quad-shuffle cell update. Weight split 46 reg / 18 smem pairs.
__global__ void __launch_bounds__(512) k_lstm(
    const float* __restrict__ Whh,
    const float* __restrict__ eps,
    const float* __restrict__ muW, const float* __restrict__ mub,
    const float* __restrict__ lvW, const float* __restrict__ lvb,
    const float* __restrict__ fcW, const float* __restrict__ fcb,
    const float* __restrict__ gWih, const float* __restrict__ gbih,
    float* __restrict__ out)
{
    extern __shared__ float sm[];
    ulonglong2* wsu2 = (ulonglong2*)sm;          // [9][512]: k=92..127
    float* hs = sm + 18432;                      // 128
    float* mu_s = hs + 128;                      // 64
    float* lv_s = mu_s + 64;                     // 64
    float* emb  = lv_s + 64;                     // 64
    float* xs   = emb + 64;                      // 256
    int tid = threadIdx.x, b = blockIdx.x;
    int gate = tid & 3, cell = tid >> 2;
    int grow = gate*HD + cell;

    const ulonglong2* wrow = (const ulonglong2*)(Whh + (size_t)grow*HD);
    unsigned long long wr2[46];                  // pairs 0..45 (k=0..91)
#pragma unroll
    for (int i = 0; i < 23; i++){
        ulonglong2 v = wrow[i];
        wr2[2*i] = v.x; wr2[2*i+1] = v.y;
    }
#pragma unroll
    for (int i = 0; i < 9; i++) wsu2[i*512 + tid] = wrow[23+i];
    if (tid < HD) hs[tid] = 0.f;
    float c = 0.f;
    __syncthreads();
    const float* xg = g_xg + b*HG + grow;
    float xcur = xg[0];
    for (int t = 0; t < TT; t++){
        float xnext = (t < TT-1) ? xg[(size_t)(t+1)*(BB*HG)] : 0.f;
        const ulonglong2* H2 = (const ulonglong2*)hs;
        unsigned long long a2 = 0ull, c2 = 0ull, d2 = 0ull, e2 = 0ull;
#pragma unroll
        for (int i = 0; i < 11; i++){                   // pairs 0..43, H2[0..21]
            ulonglong2 h0 = H2[2*i], h1 = H2[2*i+1];
            fma2(a2, wr2[4*i],   h0.x);
            fma2(c2, wr2[4*i+1], h0.y);
            fma2(d2, wr2[4*i+2], h1.x);
            fma2(e2, wr2[4*i+3], h1.y);
        }
        {                                               // pairs 44,45 <- H2[22]
            ulonglong2 h = H2[22];
            fma2(a2, wr2[44], h.x);
            fma2(c2, wr2[45], h.y);
        }
#pragma unroll
        for (int i = 0; i < 4; i++){                    // rows 0..7 <- H2[23..30]
            ulonglong2 w0 = wsu2[(2*i)*512 + tid];
            ulonglong2 w1 = wsu2[(2*i+1)*512 + tid];
            ulonglong2 h0 = H2[23+2*i], h1 = H2[24+2*i];
            fma2(a2, w0.x, h0.x);
            fma2(c2, w0.y, h0.y);
            fma2(d2, w1.x, h1.x);
            fma2(e2, w1.y, h1.y);
        }
        {                                               // row 8 <- H2[31]
            ulonglong2 w = wsu2[8*512 + tid];
            ulonglong2 h = H2[31];
            fma2(d2, w.x, h.x);
            fma2(e2, w.y, h.y);
        }
        float a0,a1,b0,b1,d0,d1,e0,e1;
        asm("mov.b64 {%0,%1}, %2;" : "=f"(a0), "=f"(a1) : "l"(a2));
        asm("mov.b64 {%0,%1}, %2;" : "=f"(b0), "=f"(b1) : "l"(c2));
        asm("mov.b64 {%0,%1}, %2;" : "=f"(d0), "=f"(d1) : "l"(d2));
        asm("mov.b64 {%0,%1}, %2;" : "=f"(e0), "=f"(e1) : "l"(e2));
        float s = xcur + ((a0+a1) + (b0+b1)) + ((d0+d1) + (e0+e1));
        float v = (gate == 2) ? tanhf(s) : sigmoidf_(s);
        float w = __shfl_xor_sync(0xffffffffu, v, 2);
        float pr = v * w;
        float x1 = __shfl_xor_sync(0xffffffffu, pr, 1);
        if (gate == 1){
            c = v*c + x1;
            hs[cell] = w * tanhf(c);
        }
        __syncthreads();
        xcur = xnext;
    }
    if (tid < 2*ZD){
        int o = tid & 63;
        const float* W = (tid < ZD) ? (muW + o*HD) : (lvW + o*HD);
        float acc = (tid < ZD) ? mub[o] : lvb[o];
        for (int k = 0; k < HD; k++) acc += W[k]*hs[k];
        acc = leakyf_(acc, 0.1f);
        if (tid < ZD) mu_s[o] = acc;
        else          lv_s[o] = fminf(10.f, fmaxf(-10.f, acc));
    }
    __syncthreads();
    if (tid < ZD){
        float m = mu_s[tid], lv = lv_s[tid];
        out[BB*TT*9 + b*ZD + tid] = m;
        out[BB*TT*9 + BB*ZD + b*ZD + tid] = lv;
        emb[tid] = m + eps[b*ZD + tid]*expf(0.5f*lv);
    }
    __syncthreads();
    if (tid < XD){
        float acc = fcb[tid];
        const float* W = fcW + tid*ZD;
        for (int k = 0; k < ZD; k++) acc += W[k]*emb[k];
        xs[tid] = acc;
    }
    __syncthreads();
    for (int g = tid; g < GG; g += 512){
        float acc = gbih[g];
        const float* W = gWih + (size_t)g*GH;
        for (int k = 0; k < XD; k++) acc += W[k]*xs[k];
        g_gxbase[(size_t)b*GG + g] = acc;
    }
}

// K5: GRU scan + pipelined jf head. 928 threads, 2 batches/block, tail interleaved.
__global__ void __launch_bounds__(928) k_gru(
    const float* __restrict__ noise_eps,
    const float* __restrict__ gWih, const float* __restrict__ gWhh,
    const float* __restrict__ gbhh,
    const float* __restrict__ b1,
    const float* __restrict__ W2, const float* __restrict__ b2,
    float* __restrict__ out)
{
    extern __shared__ float sm[];
    ulonglong2* wsA = (ulonglong2*)sm;   // [16][784]: k=32..95 pair-pairs
    float* hb0  = sm + 50176;
    float* hb1  = hb0 + 264;
    float* sums = hb1 + 264;             // [2][784]
    float* ghn  = sums + 2*784;          // [2][264]
    float* f1s  = ghn + 2*264;           // [2][64]
    float* nsAll= f1s + 128;             // [TT][8]
    int tid = threadIdx.x;
    int b0 = blockIdx.x*2;

    for (int j = tid; j < 528; j += 928) hb0[j] = 0.f;
    for (int j = tid; j < TT*8; j += 928){
        int t = j >> 3, r = j & 7, bb = r >> 2, jj = r & 3;
        nsAll[j] = noise_eps[t*(BB*4) + (b0+bb)*4 + jj] * 0.1f;
    }

    unsigned long long wr2[16];
    float w260=0,wn0=0,wn1=0,wn2=0,wn3=0,wt=0,bh=0,gx0b=0,gx1b=0;
    if (tid < GG){
        const float* row = gWhh + (size_t)tid*GH;
#pragma unroll
        for (int i = 0; i < 16; i++)
            asm("mov.b64 %0, {%1,%2};" : "=l"(wr2[i]) : "f"(row[2*i]), "f"(row[2*i+1]));
#pragma unroll
        for (int i = 0; i < 16; i++){
            ulonglong2 w;
            asm("mov.b64 %0, {%1,%2};" : "=l"(w.x) : "f"(row[32+4*i]), "f"(row[33+4*i]));
            asm("mov.b64 %0, {%1,%2};" : "=l"(w.y) : "f"(row[34+4*i]), "f"(row[35+4*i]));
            wsA[i*784 + tid] = w;
        }
        w260 = row[260];
        const float* Wi = gWih + (size_t)tid*GH;
        wn0=Wi[256]; wn1=Wi[257]; wn2=Wi[258]; wn3=Wi[259]; wt=Wi[260];
        bh = gbhh[tid];
        gx0b = g_gxbase[b0*GG + tid];
        gx1b = g_gxbase[(b0+1)*GG + tid];
    }
    __syncthreads();
    const float inv = 1.0f/(float)(TT-1);
    for (int t = 0; t <= TT; t++){
        if (t < TT && tid < GG){
            const float* nsp = nsAll + t*8;
            float tv = (float)t * inv;
            float gx0 = gx0b + wn0*nsp[0]+wn1*nsp[1]+wn2*nsp[2]+wn3*nsp[3] + wt*tv;
            float gx1 = gx1b + wn0*nsp[4]+wn1*nsp[5]+wn2*nsp[6]+wn3*nsp[7] + wt*tv;
            unsigned long long a0p = 0ull, a1p = 0ull;
            unsigned long long t0p = 0ull, t1p = 0ull;
            const ulonglong2* H0 = (const ulonglong2*)hb0;
            const ulonglong2* H1 = (const ulonglong2*)hb1;
            const ulonglong2* wp = (const ulonglong2*)g_gWhh4 + tid;
#pragma unroll
            for (int i = 0; i < 8; i++){
                ulonglong2 h0 = H0[i], h1 = H1[i];
                fma2(a0p, wr2[2*i],   h0.x);  fma2(a1p, wr2[2*i],   h1.x);
                fma2(a0p, wr2[2*i+1], h0.y);  fma2(a1p, wr2[2*i+1], h1.y);
            }
#pragma unroll 4
            for (int i = 0; i < 16; i++){
                ulonglong2 wt0 = wp[(size_t)(2*i)*GG];
                ulonglong2 wt1 = wp[(size_t)(2*i+1)*GG];
                ulonglong2 w = wsA[i*784 + tid];
                ulonglong2 h0 = H0[8+i], h1 = H1[8+i];
                fma2(a0p, w.x, h0.x);  fma2(a1p, w.x, h1.x);
                fma2(a0p, w.y, h0.y);  fma2(a1p, w.y, h1.y);
                ulonglong2 th0a = H0[24+2*i], th1a = H1[24+2*i];
                ulonglong2 th0b = H0[25+2*i], th1b = H1[25+2*i];
                fma2(t0p, wt0.x, th0a.x);  fma2(t1p, wt0.x, th1a.x);
                fma2(t0p, wt0.y, th0a.y);  fma2(t1p, wt0.y, th1a.y);
                fma2(t0p, wt1.x, th0b.x);  fma2(t1p, wt1.x, th1b.x);
                fma2(t0p, wt1.y, th0b.y);  fma2(t1p, wt1.y, th1b.y);
            }
#pragma unroll 3
            for (int p = 32; p < 41; p++){
                ulonglong2 w = wp[(size_t)p*GG];
                ulonglong2 h0 = H0[24+p], h1 = H1[24+p];
                fma2(t0p, w.x, h0.x);  fma2(t1p, w.x, h1.x);
                fma2(t0p, w.y, h0.y);  fma2(t1p, w.y, h1.y);
            }
            float s00,s01,s10,s11,u00,u01,u10,u11;
            asm("mov.b64 {%0,%1}, %2;" : "=f"(s00), "=f"(s01) : "l"(a0p));
            asm("mov.b64 {%0,%1}, %2;" : "=f"(s10), "=f"(s11) : "l"(a1p));
            asm("mov.b64 {%0,%1}, %2;" : "=f"(u00), "=f"(u01) : "l"(t0p));
            asm("mov.b64 {%0,%1}, %2;" : "=f"(u10), "=f"(u11) : "l"(t1p));
            float gh0 = bh + ((s00+s01) + (u00+u01)) + w260*hb0[260];
            float gh1 = bh + ((s10+s11) + (u10+u11)) + w260*hb1[260];
            float v0 = gx0 + gh0, v1 = gx1 + gh1;
            if (tid >= 522){
                v0 = gx0; v1 = gx1;
                ghn[tid-522] = gh0; ghn[264 + tid-522] = gh1;
            }
            sums[tid] = v0; sums[784 + tid] = v1;
        }
        if (t >= 1 && tid >= 800){
            int q = tid - 800, bb = q >> 6, o = q & 63;
            const float4* hv = (const float4*)(bb ? hb1 : hb0);
            const float4* Wv = g_W1T4 + o;
            float acc = b1[o];
#pragma unroll
            for (int p = 0; p < 66; p++){
                float4 w = Wv[p*ZD];
                float4 h = hv[p];
                acc += w.x*h.x + w.y*h.y + w.z*h.z + w.w*h.w;
            }
            f1s[bb*64 + o] = leakyf_(acc, 0.2f);
        }
        __syncthreads();
        if (t < TT && tid < 522){
            int bb = tid/261, j = tid - bb*261;
            float* hb = bb ? hb1 : hb0;
            const float* s = sums + bb*784;
            float r = sigmoidf_(s[j]);
            float z = sigmoidf_(s[261+j]);
            float n = tanhf(s[522+j] + r*ghn[bb*264 + j]);
            hb[j] = (1.f - z)*n + z*hb[j];
        }
        if (t >= 1 && tid >= 800 && tid < 818){
            int q = tid - 800, bb = q/9, i = q - bb*9;
            float acc = b2[i];
            const float* W = W2 + i*ZD;
            for (int o = 0; o < ZD; o++) acc += W[o]*f1s[bb*64 + o];
            out[(size_t)(b0+bb)*(TT*9) + (t-1)*9 + i] = sigmoidf_(acc);
        }
        __syncthreads();
    }
}

extern "C" void kernel_launch(void* const* d_in, const int* in_sizes, int n_in,
                              void* d_out, int out_size)
{
    const float* input_data = (const float*)d_in[0];
    const float* eps        = (const float*)d_in[1];
    const float* noise_eps  = (const float*)d_in[2];
    const float* proj_W     = (const float*)d_in[3];
    const float* proj_b     = (const float*)d_in[4];
    const float* lstm_Wih   = (const float*)d_in[5];
    const float* lstm_Whh   = (const float*)d_in[6];
    const float* lstm_bih   = (const float*)d_in[7];
    const float* lstm_bhh   = (const float*)d_in[8];
    const float* mu_W       = (const float*)d_in[9];
    const float* mu_b       = (const float*)d_in[10];
    const float* lv_W       = (const float*)d_in[11];
    const float* lv_b       = (const float*)d_in[12];
    const float* fcin_W     = (const float*)d_in[13];
    const float* fcin_b     = (const float*)d_in[14];
    const float* gru_Wih    = (const float*)d_in[15];
    const float* gru_Whh    = (const float*)d_in[16];
    const float* gru_bih    = (const float*)d_in[17];
    const float* gru_bhh    = (const float*)d_in[18];
    const float* jf_W1      = (const float*)d_in[19];
    const float* jf_b1      = (const float*)d_in[20];
    const float* jf_W2      = (const float*)d_in[21];
    const float* jf_b2      = (const float*)d_in[22];
    float* out = (float*)d_out;

    int gemm_smem = 2*2*128*SMSH*2;
    int lstm_smem = 18432*4 + (128 + 64 + 64 + 64 + 256)*4;
    int gru_smem  = (50176 + 264 + 264 + 2*784 + 2*264 + 128 + TT*8)*4;
    cudaFuncSetAttribute(k_gemm, cudaFuncAttributeMaxDynamicSharedMemorySize, gemm_smem);
    cudaFuncSetAttribute(k_lstm, cudaFuncAttributeMaxDynamicSharedMemorySize, lstm_smem);
    cudaFuncSetAttribute(k_gru,  cudaFuncAttributeMaxDynamicSharedMemorySize, gru_smem);

    k_proj<<<1760, 512>>>(input_data, proj_W, proj_b,
                          lstm_Wih, gru_Whh, jf_W1);
    dim3 g2(HG/128, TT*BB/128);
    k_gemm<<<g2, 256, gemm_smem>>>(lstm_bih, lstm_bhh);
    k_lstm<<<BB, 512, lstm_smem>>>(lstm_Whh, eps, mu_W, mu_b, lv_W, lv_b,
                                   fcin_W, fcin_b, gru_Wih, gru_bih, out);
    k_gru<<<BB/2, 928, gru_smem>>>(noise_eps, gru_Wih, gru_Whh, gru_bhh,
                                   jf_b1, jf_W2, jf_b2, out);
}